// round 15
// baseline (speedup 1.0000x reference)
#include <cuda_runtime.h>
#include <cuda_bf16.h>
#include <cstdint>

// Problem constants
#define NN 20000
#define EE 320000
#define EP (EE + NN)          // 340000
#define BB 128
#define HID 64
#define HEADS 4
#define DD 256
#define CAT 576
#define ENC_H 512
#define DUEL_H 128

// ================= scratch (static device memory) ============================
__device__ float g_xlr[NN * 512];     // [xl | xr] per row
__device__ float g_h3[NN * DD];
__device__ float g_b1[512], g_b2[512];  // pooled conv biases [bl | br]
__device__ int   g_deg[NN];
__device__ int   g_off[NN + 1];
__device__ int   g_pos[NN];
__device__ int   g_src[EP];           // CSR payload: source node id (direct)
// bf16 hi/lo activations
__device__ __nv_bfloat16 g_xh[NN * HID],      g_xlo[NN * HID];
__device__ __nv_bfloat16 g_h512h[NN * ENC_H], g_h512l[NN * ENC_H];
__device__ __nv_bfloat16 g_hh[NN * HID],      g_hl[NN * HID];
__device__ __nv_bfloat16 g_h2h[NN * DD],      g_h2l[NN * DD];
// transposed bf16 hi/lo weights, packed pool  (layout [N][K]); WL/WR pairs contiguous
#define WOFF_ENC1 0          // [512][64]
#define WOFF_ENC2 32768      // [64][512]
#define WOFF_W1   65536      // [512][64]  (wl1 || wr1)
#define WOFF_W2   98304      // [512][256] (wl2 || wr2)
#define WPOOL     229376
__device__ __nv_bfloat16 g_wth[WPOOL], g_wtl[WPOOL];

__device__ __forceinline__ void split_bf16(float v, __nv_bfloat16& hi, __nv_bfloat16& lo) {
    hi = __float2bfloat16(v);
    lo = __float2bfloat16(v - __bfloat162float(hi));
}

__device__ __forceinline__ uint32_t smem_u32(const void* p) {
    uint32_t a;
    asm("{ .reg .u64 t; cvta.to.shared.u64 t, %1; cvt.u32.u64 %0, t; }" : "=r"(a) : "l"(p));
    return a;
}
__device__ __forceinline__ void cp16(uint32_t d, const void* s, int sz) {
    asm volatile("cp.async.cg.shared.global [%0], [%1], 16, %2;" :: "r"(d), "l"(s), "r"(sz));
}
#define CP_COMMIT() asm volatile("cp.async.commit_group;" ::: "memory")
#define CP_WAIT(n)  asm volatile("cp.async.wait_group %0;" :: "n"(n) : "memory")

// bf16 mma.sync + ldmatrix (sm_75/80+ baseline; valid on plain sm_103 target)
__device__ __forceinline__ void mma16816(float* c, const uint32_t* a, const uint32_t* b) {
    asm volatile(
        "mma.sync.aligned.m16n8k16.row.col.f32.bf16.bf16.f32 "
        "{%0,%1,%2,%3}, {%4,%5,%6,%7}, {%8,%9}, {%0,%1,%2,%3};"
        : "+f"(c[0]), "+f"(c[1]), "+f"(c[2]), "+f"(c[3])
        : "r"(a[0]), "r"(a[1]), "r"(a[2]), "r"(a[3]), "r"(b[0]), "r"(b[1]));
}
__device__ __forceinline__ void ldsm_x4(uint32_t* r, uint32_t addr) {
    asm volatile("ldmatrix.sync.aligned.m8n8.x4.shared.b16 {%0,%1,%2,%3}, [%4];"
        : "=r"(r[0]), "=r"(r[1]), "=r"(r[2]), "=r"(r[3]) : "r"(addr));
}

#define LEAKY(v) ((v) > 0.f ? (v) : 0.2f * (v))

// ================= prep kernels ==============================================
__global__ void k_split_x(const float* __restrict__ x) {
    int i = (blockIdx.x * blockDim.x + threadIdx.x) * 4;
    if (i >= NN * HID) return;
    float4 v = *(const float4*)&x[i];
    __nv_bfloat162 h0, h1, l0, l1;
    split_bf16(v.x, h0.x, l0.x); split_bf16(v.y, h0.y, l0.y);
    split_bf16(v.z, h1.x, l1.x); split_bf16(v.w, h1.y, l1.y);
    *(__nv_bfloat162*)&g_xh[i]      = h0;
    *(__nv_bfloat162*)&g_xh[i + 2]  = h1;
    *(__nv_bfloat162*)&g_xlo[i]     = l0;
    *(__nv_bfloat162*)&g_xlo[i + 2] = l1;
}

__global__ void k_wprep(const float* __restrict__ w0, const float* __restrict__ w1,
                        const float* __restrict__ w2, const float* __restrict__ w3,
                        const float* __restrict__ w4, const float* __restrict__ w5) {
    int blk = blockIdx.x;
    const float* src; int K_, N_, dst, start;
    if      (blk < 128) { src = w0; K_ = 64;  N_ = 512; dst = WOFF_ENC1;        start = 0;   }
    else if (blk < 256) { src = w1; K_ = 512; N_ = 64;  dst = WOFF_ENC2;        start = 128; }
    else if (blk < 320) { src = w2; K_ = 64;  N_ = 256; dst = WOFF_W1;          start = 256; }
    else if (blk < 384) { src = w3; K_ = 64;  N_ = 256; dst = WOFF_W1 + 16384;  start = 320; }
    else if (blk < 640) { src = w4; K_ = 256; N_ = 256; dst = WOFF_W2;          start = 384; }
    else                { src = w5; K_ = 256; N_ = 256; dst = WOFF_W2 + 65536;  start = 640; }
    int e = (blk - start) * 256 + threadIdx.x;
    if (e >= K_ * N_) return;
    int n = e / K_, k = e % K_;
    split_bf16(src[(size_t)k * N_ + n], g_wth[dst + e], g_wtl[dst + e]);
}

__global__ void k_bprep(const float* __restrict__ bl1, const float* __restrict__ br1,
                        const float* __restrict__ bl2, const float* __restrict__ br2) {
    int t = blockIdx.x * blockDim.x + threadIdx.x;
    if (t >= 1024) return;
    if (t < 256)       g_b1[t] = bl1[t];
    else if (t < 512)  g_b1[t] = br1[t - 256];
    else if (t < 768)  g_b2[t - 512] = bl2[t - 512];
    else               g_b2[t - 512] = br2[t - 768];
}

// ================= CSR build ================================================
__global__ void k_zero_deg() {
    int i = blockIdx.x * blockDim.x + threadIdx.x;
    if (i < NN) g_deg[i] = 0;
}
__global__ void k_count(const int* __restrict__ EI) {
    int e = blockIdx.x * blockDim.x + threadIdx.x;
    if (e >= EP) return;
    int dst = (e < EE) ? EI[EE + e] : (e - EE);
    atomicAdd(&g_deg[dst], 1);
}
__global__ void k_scan() {
    const int CH = (NN + 1023) / 1024;
    __shared__ int part[1024];
    int t = threadIdx.x, base = t * CH, local[CH], s = 0;
#pragma unroll
    for (int i = 0; i < CH; i++) {
        int idx = base + i;
        int v = (idx < NN) ? g_deg[idx] : 0;
        local[i] = s; s += v;
    }
    part[t] = s;
    __syncthreads();
    for (int o = 1; o < 1024; o <<= 1) {
        int v = (t >= o) ? part[t - o] : 0;
        __syncthreads();
        part[t] += v;
        __syncthreads();
    }
    int ex0 = (t == 0) ? 0 : part[t - 1];
#pragma unroll
    for (int i = 0; i < CH; i++) {
        int idx = base + i;
        if (idx < NN) { int v = ex0 + local[i]; g_off[idx] = v; g_pos[idx] = v; }
    }
    if (t == 1023) g_off[NN] = ex0 + s;
}
__global__ void k_fill(const int* __restrict__ EI) {
    int e = blockIdx.x * blockDim.x + threadIdx.x;
    if (e >= EP) return;
    int dst, src;
    if (e < EE) { src = EI[e]; dst = EI[EE + e]; }
    else        { src = dst = e - EE; }
    int p = atomicAdd(&g_pos[dst], 1);
    g_src[p] = src;
}

// ================= HMMA GEMM (cp.async 2-stage pipeline + ldmatrix) ==========
#define STR 40
template <int BM, int BN, int MAXB, int ACT, int WF32, int WB16>
__global__ __launch_bounds__(256, MAXB)
void k_mma(const __nv_bfloat16* __restrict__ Ah, const __nv_bfloat16* __restrict__ Al,
           const __nv_bfloat16* __restrict__ Bh, const __nv_bfloat16* __restrict__ Bl,
           const float* __restrict__ bias, float* __restrict__ Cf,
           __nv_bfloat16* __restrict__ Ch, __nv_bfloat16* __restrict__ Cl,
           int M, int K, int Nn) {
    constexpr int WROWS = BM / 32;
    constexpr int WCOLS = 8 / WROWS;
    constexpr int WNT = BN / WCOLS;
    constexpr int NF = WNT / 8;
    constexpr int STAGE = (2 * BM + 2 * BN) * STR;
    extern __shared__ __nv_bfloat16 smem[];

    const int tid = threadIdx.x;
    const int warp = tid >> 5;
    const int lane = tid & 31;
    const int gid = lane >> 2;
    const int tid4 = lane & 3;
    const int wR = warp / WCOLS;
    const int wC = warp % WCOLS;
    const int rowBase = blockIdx.y * BM;
    const int colBase = blockIdx.x * BN;

    const int q = lane >> 3;
    const int ri = lane & 7;
    const int aRow = wR * 32 + ri + (q & 1) * 8;
    const int aCol = (q >> 1) * 8;
    const int bRow = wC * WNT + ri + (q >> 1) * 8;
    const int bCol = (q & 1) * 8;

    const uint32_t sbase = smem_u32(smem);
    constexpr int offAl = BM * STR;
    constexpr int offBh = 2 * BM * STR;
    constexpr int offBl = 2 * BM * STR + BN * STR;

    float acc[2][NF][4];
#pragma unroll
    for (int i = 0; i < 2; i++)
#pragma unroll
        for (int j = 0; j < NF; j++)
#pragma unroll
            for (int qq = 0; qq < 4; qq++) acc[i][j][qq] = 0.f;

    const int chunks = K >> 5;

    auto load_stage = [&](int st, int c) {
        __nv_bfloat16* dAh = smem + st * STAGE;
        __nv_bfloat16* dAl = dAh + BM * STR;
        __nv_bfloat16* dBh = dAl + BM * STR;
        __nv_bfloat16* dBl = dBh + BN * STR;
#pragma unroll
        for (int v = tid; v < BM * 4; v += 256) {
            int r = v >> 2, c4 = v & 3;
            int gr = rowBase + r;
            int sz = (gr < M) ? 16 : 0;
            size_t gi = (size_t)gr * K + c * 32 + c4 * 8;
            cp16(smem_u32(dAh + r * STR + c4 * 8), &Ah[gi], sz);
            cp16(smem_u32(dAl + r * STR + c4 * 8), &Al[gi], sz);
        }
#pragma unroll
        for (int v = tid; v < BN * 4; v += 256) {
            int r = v >> 2, c4 = v & 3;
            size_t gi = (size_t)(colBase + r) * K + c * 32 + c4 * 8;
            cp16(smem_u32(dBh + r * STR + c4 * 8), &Bh[gi], 16);
            cp16(smem_u32(dBl + r * STR + c4 * 8), &Bl[gi], 16);
        }
    };

    load_stage(0, 0);
    CP_COMMIT();

    for (int c = 0; c < chunks; c++) {
        if (c + 1 < chunks) {
            load_stage((c + 1) & 1, c + 1);
            CP_COMMIT();
            CP_WAIT(1);
        } else {
            CP_WAIT(0);
        }
        __syncthreads();

        const uint32_t stE = (uint32_t)((c & 1) * STAGE);
        const uint32_t aAddr = sbase + (stE + (uint32_t)(aRow * STR + aCol)) * 2;
        const uint32_t bAddr = sbase + (stE + (uint32_t)(bRow * STR + bCol)) * 2;

#pragma unroll
        for (int ks = 0; ks < 2; ks++) {
            uint32_t ah[2][4], al[2][4];
#pragma unroll
            for (int mf = 0; mf < 2; mf++) {
                uint32_t a = aAddr + (uint32_t)(mf * 16 * STR + ks * 16) * 2;
                ldsm_x4(ah[mf], a);
                ldsm_x4(al[mf], a + offAl * 2);
            }
#pragma unroll
            for (int nfp = 0; nfp < NF / 2; nfp++) {
                uint32_t bh[4], bl[4];
                uint32_t b = bAddr + (uint32_t)(nfp * 16 * STR + ks * 16) * 2;
                ldsm_x4(bh, b + offBh * 2);
                ldsm_x4(bl, b + offBl * 2);
#pragma unroll
                for (int j = 0; j < 2; j++) {
                    int nf = nfp * 2 + j;
#pragma unroll
                    for (int mf = 0; mf < 2; mf++) {
                        mma16816(acc[mf][nf], ah[mf], &bh[2 * j]);
                        mma16816(acc[mf][nf], ah[mf], &bl[2 * j]);
                        mma16816(acc[mf][nf], al[mf], &bh[2 * j]);
                    }
                }
            }
        }
        __syncthreads();
    }

    // epilogue: bias + act (+ bf16 split), straight from fragments
#pragma unroll
    for (int nf = 0; nf < NF; nf++) {
        int col = colBase + wC * WNT + nf * 8 + tid4 * 2;
        float b0 = bias[col], b1 = bias[col + 1];
#pragma unroll
        for (int mf = 0; mf < 2; mf++) {
#pragma unroll
            for (int half = 0; half < 2; half++) {
                int row = rowBase + wR * 32 + mf * 16 + gid + half * 8;
                if (row >= M) continue;
                float v0 = acc[mf][nf][half * 2] + b0;
                float v1 = acc[mf][nf][half * 2 + 1] + b1;
                if (ACT == 1) { v0 = fmaxf(v0, 0.f); v1 = fmaxf(v1, 0.f); }
                size_t oi = (size_t)row * Nn + col;
                if (WF32) *(float2*)&Cf[oi] = make_float2(v0, v1);
                if (WB16) {
                    __nv_bfloat162 hh2, ll2;
                    split_bf16(v0, hh2.x, ll2.x);
                    split_bf16(v1, hh2.y, ll2.y);
                    *(__nv_bfloat162*)&Ch[oi] = hh2;
                    *(__nv_bfloat162*)&Cl[oi] = ll2;
                }
            }
        }
    }
}

// ================= persistent K=64 GEMM: B resident, loop over G M-tiles ======
// BM=BN=64, K=64. B tile loaded once; B fragments hoisted to registers.
// A double-buffered across M-tiles with cp.async overlap.
#define STR2 72
template <int G, int ACT, int WF32, int WB16>
__global__ __launch_bounds__(256, 3)
void k_mma_p(const __nv_bfloat16* __restrict__ Ah, const __nv_bfloat16* __restrict__ Al,
             const __nv_bfloat16* __restrict__ Bh, const __nv_bfloat16* __restrict__ Bl,
             const float* __restrict__ bias, float* __restrict__ Cf,
             __nv_bfloat16* __restrict__ Ch, __nv_bfloat16* __restrict__ Cl,
             int M, int Nn) {
    constexpr int TILE = 64 * STR2;            // elements per matrix tile
    extern __shared__ __nv_bfloat16 smem[];
    __nv_bfloat16* sBh = smem;                 // [0, TILE)
    __nv_bfloat16* sBl = sBh + TILE;
    __nv_bfloat16* sA  = sBl + TILE;           // 2 stages x (Ah TILE + Al TILE)

    const int tid = threadIdx.x;
    const int warp = tid >> 5;
    const int lane = tid & 31;
    const int gid = lane >> 2;
    const int tid4 = lane & 3;
    const int wR = warp >> 2;        // 2 warp-rows
    const int wC = warp & 3;         // 4 warp-cols, WNT=16, NF=2
    const int colBase = blockIdx.x * 64;
    const int mBase = blockIdx.y * G;

    const int q = lane >> 3;
    const int ri = lane & 7;
    const int aRow = wR * 32 + ri + (q & 1) * 8;
    const int aCol = (q >> 1) * 8;
    const int bRow = wC * 16 + ri + (q >> 1) * 8;
    const int bCol = (q & 1) * 8;

    const uint32_t sbase = smem_u32(smem);
    const uint32_t aBase = sbase + (uint32_t)(2 * TILE) * 2;   // byte offset of sA

    // ---- load B (full 64x64, both hi/lo), plus A tile for g=0 ----
    auto load_A = [&](int st, int g) {
        __nv_bfloat16* dAh = sA + st * (2 * TILE);
        __nv_bfloat16* dAl = dAh + TILE;
        int rowB = (mBase + g) * 64;
#pragma unroll
        for (int v = tid; v < 64 * 8; v += 256) {
            int r = v >> 3, c8 = v & 7;
            int gr = rowB + r;
            int sz = (gr < M) ? 16 : 0;
            size_t gi = (size_t)gr * 64 + c8 * 8;
            cp16(smem_u32(dAh + r * STR2 + c8 * 8), &Ah[gi], sz);
            cp16(smem_u32(dAl + r * STR2 + c8 * 8), &Al[gi], sz);
        }
    };

#pragma unroll
    for (int v = tid; v < 64 * 8; v += 256) {
        int r = v >> 3, c8 = v & 7;
        size_t gi = (size_t)(colBase + r) * 64 + c8 * 8;
        cp16(smem_u32(sBh + r * STR2 + c8 * 8), &Bh[gi], 16);
        cp16(smem_u32(sBl + r * STR2 + c8 * 8), &Bl[gi], 16);
    }
    CP_COMMIT();
    load_A(0, 0);
    CP_COMMIT();
    CP_WAIT(0);
    __syncthreads();

    // ---- hoist B fragments to registers: 4 ks x (bh[4], bl[4]) ----
    uint32_t bhR[4][4], blR[4][4];
#pragma unroll
    for (int ks = 0; ks < 4; ks++) {
        uint32_t b = sbase + (uint32_t)(bRow * STR2 + bCol + ks * 16) * 2;
        ldsm_x4(bhR[ks], b);
        ldsm_x4(blR[ks], b + TILE * 2);
    }

    // bias regs (per-thread columns fixed across tiles)
    float bv[2][2];
#pragma unroll
    for (int nf = 0; nf < 2; nf++) {
        int col = colBase + wC * 16 + nf * 8 + tid4 * 2;
        bv[nf][0] = bias[col];
        bv[nf][1] = bias[col + 1];
    }

    for (int g = 0; g < G; g++) {
        if (g > 0) {
            CP_WAIT(0);
        }
        __syncthreads();
        if (g + 1 < G) {
            load_A((g + 1) & 1, g + 1);
            CP_COMMIT();
        }

        float acc[2][2][4];
#pragma unroll
        for (int i = 0; i < 2; i++)
#pragma unroll
            for (int j = 0; j < 2; j++)
#pragma unroll
                for (int qq = 0; qq < 4; qq++) acc[i][j][qq] = 0.f;

        const uint32_t aAddr = aBase + (uint32_t)((g & 1) * (2 * TILE)) * 2
                             + (uint32_t)(aRow * STR2 + aCol) * 2;
#pragma unroll
        for (int ks = 0; ks < 4; ks++) {
            uint32_t ah[2][4], al[2][4];
#pragma unroll
            for (int mf = 0; mf < 2; mf++) {
                uint32_t a = aAddr + (uint32_t)(mf * 16 * STR2 + ks * 16) * 2;
                ldsm_x4(ah[mf], a);
                ldsm_x4(al[mf], a + TILE * 2);
            }
#pragma unroll
            for (int j = 0; j < 2; j++) {
#pragma unroll
                for (int mf = 0; mf < 2; mf++) {
                    mma16816(acc[mf][j], ah[mf], &bhR[ks][2 * j]);
                    mma16816(acc[mf][j], ah[mf], &blR[ks][2 * j]);
                    mma16816(acc[mf][j], al[mf], &bhR[ks][2 * j]);
                }
            }
        }

        // epilogue for this M-tile
        int rowB = (mBase + g) * 64;
#pragma unroll
        for (int nf = 0; nf < 2; nf++) {
            int col = colBase + wC * 16 + nf * 8 + tid4 * 2;
#pragma unroll
            for (int mf = 0; mf < 2; mf++) {
#pragma unroll
                for (int half = 0; half < 2; half++) {
                    int row = rowB + wR * 32 + mf * 16 + gid + half * 8;
                    if (row >= M) continue;
                    float v0 = acc[mf][nf][half * 2] + bv[nf][0];
                    float v1 = acc[mf][nf][half * 2 + 1] + bv[nf][1];
                    if (ACT == 1) { v0 = fmaxf(v0, 0.f); v1 = fmaxf(v1, 0.f); }
                    size_t oi = (size_t)row * Nn + col;
                    if (WF32) *(float2*)&Cf[oi] = make_float2(v0, v1);
                    if (WB16) {
                        __nv_bfloat162 hh2, ll2;
                        split_bf16(v0, hh2.x, ll2.x);
                        split_bf16(v1, hh2.y, ll2.y);
                        *(__nv_bfloat162*)&Ch[oi] = hh2;
                        *(__nv_bfloat162*)&Cl[oi] = ll2;
                    }
                }
            }
        }
    }
}

// ================= fused GATv2 layer (4-edge unrolled, round-12 form) ========
// xlr: [NN][512], xl = cols 0..255, xr = cols 256..511
template <bool WB16>
__global__ __launch_bounds__(128, 8)
void k_gat(const float* __restrict__ xlr,
           const float* __restrict__ att, const float* __restrict__ bias,
           float* __restrict__ out, __nv_bfloat16* outH, __nv_bfloat16* outL) {
    const int i = blockIdx.x;
    const int w = threadIdx.x >> 5;
    const int lane = threadIdx.x & 31;
    const int f = w * HID + lane * 2;
    const int s0 = g_off[i], s1 = g_off[i + 1];   // s1 > s0 (self loop)

    const float2 xrv = *(const float2*)(xlr + (size_t)i * 512 + 256 + f);
    const float2 atv = *(const float2*)(att + f);

    float acc0 = 0.f, acc1 = 0.f, den = 0.f;
    int p = s0;
    for (; p + 4 <= s1; p += 4) {
        int sA = __ldg(&g_src[p]);
        int sB = __ldg(&g_src[p + 1]);
        int sC = __ldg(&g_src[p + 2]);
        int sD = __ldg(&g_src[p + 3]);
        float2 xvA = *(const float2*)(xlr + (size_t)sA * 512 + f);
        float2 xvB = *(const float2*)(xlr + (size_t)sB * 512 + f);
        float2 xvC = *(const float2*)(xlr + (size_t)sC * 512 + f);
        float2 xvD = *(const float2*)(xlr + (size_t)sD * 512 + f);
        float sa = LEAKY(xvA.x + xrv.x) * atv.x + LEAKY(xvA.y + xrv.y) * atv.y;
        float sb = LEAKY(xvB.x + xrv.x) * atv.x + LEAKY(xvB.y + xrv.y) * atv.y;
        float sc = LEAKY(xvC.x + xrv.x) * atv.x + LEAKY(xvC.y + xrv.y) * atv.y;
        float sd = LEAKY(xvD.x + xrv.x) * atv.x + LEAKY(xvD.y + xrv.y) * atv.y;
#pragma unroll
        for (int o = 16; o; o >>= 1) {
            sa += __shfl_xor_sync(0xffffffffu, sa, o);
            sb += __shfl_xor_sync(0xffffffffu, sb, o);
            sc += __shfl_xor_sync(0xffffffffu, sc, o);
            sd += __shfl_xor_sync(0xffffffffu, sd, o);
        }
        float exa = __expf(sa), exb = __expf(sb);
        float exc = __expf(sc), exd = __expf(sd);
        acc0 += exa * xvA.x + exb * xvB.x + exc * xvC.x + exd * xvD.x;
        acc1 += exa * xvA.y + exb * xvB.y + exc * xvC.y + exd * xvD.y;
        den  += exa + exb + exc + exd;
    }
    for (; p < s1; p++) {
        int sA = __ldg(&g_src[p]);
        float2 xvA = *(const float2*)(xlr + (size_t)sA * 512 + f);
        float sa = LEAKY(xvA.x + xrv.x) * atv.x + LEAKY(xvA.y + xrv.y) * atv.y;
#pragma unroll
        for (int o = 16; o; o >>= 1) sa += __shfl_xor_sync(0xffffffffu, sa, o);
        float exa = __expf(sa);
        acc0 += exa * xvA.x; acc1 += exa * xvA.y; den += exa;
    }
    float rr = 1.f / (den + 1e-16f);
    float o0 = fmaxf(acc0 * rr + bias[f], 0.f);
    float o1 = fmaxf(acc1 * rr + bias[f + 1], 0.f);
    size_t oi = (size_t)i * DD + f;
    if (!WB16) { out[oi] = o0; out[oi + 1] = o1; }
    if (WB16) {
        __nv_bfloat162 h, l;
        split_bf16(o0, h.x, l.x); split_bf16(o1, h.y, l.y);
        *(__nv_bfloat162*)&outH[oi] = h;
        *(__nv_bfloat162*)&outL[oi] = l;
    }
}

// ================= dueling head (gathers from hi/lo pairs) ===================
__global__ void k_head(const int* __restrict__ idx,
                       const float* __restrict__ h3,
                       const float* __restrict__ qw1, const float* __restrict__ qb1,
                       const float* __restrict__ qw2, const float* __restrict__ qb2,
                       const float* __restrict__ vw1, const float* __restrict__ vb1,
                       const float* __restrict__ vw2, const float* __restrict__ vb2,
                       float* __restrict__ out) {
    __shared__ float f[CAT];
    __shared__ float r0[DUEL_H], r1[DUEL_H], r2[DUEL_H];
    int b = blockIdx.x, t = threadIdx.x;
    int n = idx[b];
    for (int i = t; i < CAT; i += DUEL_H) {
        float v;
        if (i < HID)
            v = __bfloat162float(g_hh[(size_t)n * HID + i]) +
                __bfloat162float(g_hl[(size_t)n * HID + i]);
        else if (i < HID + DD)
            v = __bfloat162float(g_h2h[(size_t)n * DD + (i - HID)]) +
                __bfloat162float(g_h2l[(size_t)n * DD + (i - HID)]);
        else
            v = h3[(size_t)n * DD + (i - HID - DD)];
        f[i] = v;
    }
    __syncthreads();
    float q = 0.f, v = 0.f;
#pragma unroll 4
    for (int k = 0; k < CAT; k++) {
        float fv = f[k];
        q += fv * qw1[(size_t)k * DUEL_H + t];
        v += fv * vw1[(size_t)k * DUEL_H + t];
    }
    q = fmaxf(q + qb1[t], 0.f);
    v = fmaxf(v + vb1[t], 0.f);
    r0[t] = q * qw2[t * 2 + 0];
    r1[t] = q * qw2[t * 2 + 1];
    r2[t] = v * vw2[t];
    __syncthreads();
    for (int o = 64; o; o >>= 1) {
        if (t < o) { r0[t] += r0[t + o]; r1[t] += r1[t + o]; r2[t] += r2[t + o]; }
        __syncthreads();
    }
    if (t == 0) {
        float q0 = r0[0] + qb2[0], q1 = r1[0] + qb2[1], vv = r2[0] + vb2[0];
        float m = 0.5f * (q0 + q1);
        out[b * 2 + 0] = q0 - m + vv;
        out[b * 2 + 1] = q1 - m + vv;
    }
}

// ================= launch ====================================================
extern "C" void kernel_launch(void* const* d_in, const int* in_sizes, int n_in,
                              void* d_out, int out_size) {
    const float* x      = (const float*)d_in[0];
    const int*   EI     = (const int*)  d_in[1];
    const int*   idx    = (const int*)  d_in[2];
    const float* enc_w1 = (const float*)d_in[3];
    const float* enc_b1 = (const float*)d_in[4];
    const float* enc_w2 = (const float*)d_in[5];
    const float* enc_b2 = (const float*)d_in[6];
    const float* wl1    = (const float*)d_in[7];
    const float* bl1    = (const float*)d_in[8];
    const float* wr1    = (const float*)d_in[9];
    const float* br1    = (const float*)d_in[10];
    const float* att1   = (const float*)d_in[11];
    const float* bias1  = (const float*)d_in[12];
    const float* wl2    = (const float*)d_in[13];
    const float* bl2    = (const float*)d_in[14];
    const float* wr2    = (const float*)d_in[15];
    const float* br2    = (const float*)d_in[16];
    const float* att2   = (const float*)d_in[17];
    const float* bias2  = (const float*)d_in[18];
    const float* q_w1   = (const float*)d_in[19];
    const float* q_b1   = (const float*)d_in[20];
    const float* q_w2   = (const float*)d_in[21];
    const float* q_b2   = (const float*)d_in[22];
    const float* v_w1   = (const float*)d_in[23];
    const float* v_b1   = (const float*)d_in[24];
    const float* v_w2   = (const float*)d_in[25];
    const float* v_b2   = (const float*)d_in[26];
    float* out = (float*)d_out;

    float *xlr, *h3, *b1, *b2;
    __nv_bfloat16 *xh, *xlo, *h512h, *h512l, *hh, *hl, *h2h, *h2l, *wth, *wtl;
    cudaGetSymbolAddress((void**)&xlr,  g_xlr);
    cudaGetSymbolAddress((void**)&h3,   g_h3);
    cudaGetSymbolAddress((void**)&b1,   g_b1);
    cudaGetSymbolAddress((void**)&b2,   g_b2);
    cudaGetSymbolAddress((void**)&xh,   g_xh);
    cudaGetSymbolAddress((void**)&xlo,  g_xlo);
    cudaGetSymbolAddress((void**)&h512h, g_h512h);
    cudaGetSymbolAddress((void**)&h512l, g_h512l);
    cudaGetSymbolAddress((void**)&hh,   g_hh);
    cudaGetSymbolAddress((void**)&hl,   g_hl);
    cudaGetSymbolAddress((void**)&h2h,  g_h2h);
    cudaGetSymbolAddress((void**)&h2l,  g_h2l);
    cudaGetSymbolAddress((void**)&wth,  g_wth);
    cudaGetSymbolAddress((void**)&wtl,  g_wtl);

    // Lazy one-time host resources for fork/join (graph-capture legal)
    static cudaStream_t s2 = nullptr, s3 = nullptr;
    static cudaEvent_t evFork = nullptr, evJoin = nullptr, evPrep = nullptr;
    if (!s2) {
        cudaStreamCreateWithFlags(&s2, cudaStreamNonBlocking);
        cudaStreamCreateWithFlags(&s3, cudaStreamNonBlocking);
        cudaEventCreateWithFlags(&evFork, cudaEventDisableTiming);
        cudaEventCreateWithFlags(&evJoin, cudaEventDisableTiming);
        cudaEventCreateWithFlags(&evPrep, cudaEventDisableTiming);
    }

    const int SM_64_64 = 2 * (2 * 64 + 2 * 64) * STR * 2;     // 40,960 B
    const int SM_PERS  = (2 + 4) * 64 * STR2 * 2;             // 55,296 B
    cudaFuncSetAttribute((const void*)k_mma<64, 64, 3, 1, 0, 1>, cudaFuncAttributeMaxDynamicSharedMemorySize, SM_64_64);
    cudaFuncSetAttribute((const void*)k_mma<64, 64, 3, 0, 1, 0>, cudaFuncAttributeMaxDynamicSharedMemorySize, SM_64_64);
    cudaFuncSetAttribute((const void*)k_mma_p<7, 1, 0, 1>, cudaFuncAttributeMaxDynamicSharedMemorySize, SM_PERS);
    cudaFuncSetAttribute((const void*)k_mma_p<7, 0, 1, 0>, cudaFuncAttributeMaxDynamicSharedMemorySize, SM_PERS);

    const int MT64 = (NN + 63) / 64;          // 313
    const int MG7  = (MT64 + 6) / 7;          // 45 M-groups

    // ---- fork: CSR build chain on s2; weight prep on s3 ----
    cudaEventRecord(evFork, 0);
    cudaStreamWaitEvent(s2, evFork, 0);
    cudaStreamWaitEvent(s3, evFork, 0);
    k_zero_deg<<<(NN + 255) / 256, 256, 0, s2>>>();
    k_count<<<(EP + 255) / 256, 256, 0, s2>>>(EI);
    k_scan<<<1, 1024, 0, s2>>>();
    k_fill<<<(EP + 255) / 256, 256, 0, s2>>>(EI);
    cudaEventRecord(evJoin, s2);

    k_wprep<<<896, 256, 0, s3>>>(enc_w1, enc_w2, wl1, wr1, wl2, wr2);
    k_bprep<<<4, 256, 0, s3>>>(bl1, br1, bl2, br2);
    cudaEventRecord(evPrep, s3);

    // ---- main stream: activation split, then GEMM chain ----
    k_split_x<<<(NN * HID / 4 + 255) / 256, 256>>>(x);
    cudaStreamWaitEvent(0, evPrep, 0);

    // enc1: [NN,64] @ [64,512] -> h512 (bf16 hi/lo), relu  (persistent K=64)
    k_mma_p<7, 1, 0, 1><<<dim3(ENC_H / 64, MG7), 256, SM_PERS>>>(
        xh, xlo, wth + WOFF_ENC1, wtl + WOFF_ENC1, enc_b1, nullptr, h512h, h512l, NN, ENC_H);
    // enc2: [NN,512] @ [512,64] -> h (bf16 hi/lo only), relu
    k_mma<64, 64, 3, 1, 0, 1><<<dim3(1, MT64), 256, SM_64_64>>>(
        h512h, h512l, wth + WOFF_ENC2, wtl + WOFF_ENC2, enc_b2, nullptr, hh, hl, NN, ENC_H, HID);

    // conv1: combined [xl|xr] transform, N=512, K=64  (persistent K=64)
    k_mma_p<7, 0, 1, 0><<<dim3(8, MG7), 256, SM_PERS>>>(
        hh, hl, wth + WOFF_W1, wtl + WOFF_W1, b1, xlr, nullptr, nullptr, NN, 512);

    // ---- join: CSR must be ready before gat1 ----
    cudaStreamWaitEvent(0, evJoin, 0);
    k_gat<true><<<NN, 128>>>(xlr, att1, bias1, nullptr, h2h, h2l);

    // conv2: combined transform, N=512, K=256
    k_mma<64, 64, 3, 0, 1, 0><<<dim3(8, MT64), 256, SM_64_64>>>(
        h2h, h2l, wth + WOFF_W2, wtl + WOFF_W2, b2, xlr, nullptr, nullptr, NN, DD, 512);
    k_gat<false><<<NN, 128>>>(xlr, att2, bias2, h3, nullptr, nullptr);

    // heads
    k_head<<<BB, DUEL_H>>>(idx, h3,
                           q_w1, q_b1, q_w2, q_b2, v_w1, v_b1, v_w2, v_b2, out);
}

// round 16
// speedup vs baseline: 1.2934x; 1.2934x over previous
#include <cuda_runtime.h>
#include <cuda_bf16.h>
#include <cstdint>

// Problem constants
#define NN 20000
#define EE 320000
#define EP (EE + NN)          // 340000
#define BB 128
#define HID 64
#define HEADS 4
#define DD 256
#define CAT 576
#define ENC_H 512
#define DUEL_H 128

// ================= scratch (static device memory) ============================
__device__ float g_xlr[NN * 512];     // conv1: [xl | xr] per row
__device__ float g_xl2[NN * DD];      // conv2: xl transform, all nodes
__device__ float g_xr2[BB * DD];      // conv2: xr transform, indexed nodes only
__device__ float g_h3[BB * DD];       // gat2 output, compact over indexed nodes
__device__ float g_b1[512], g_b2[512];  // pooled conv biases [bl | br]
__device__ int   g_deg[NN];
__device__ int   g_off[NN + 1];
__device__ int   g_pos[NN];
__device__ int   g_src[EP];           // CSR payload: source node id (direct)
// bf16 hi/lo activations
__device__ __nv_bfloat16 g_xh[NN * HID],      g_xlo[NN * HID];
__device__ __nv_bfloat16 g_h512h[NN * ENC_H], g_h512l[NN * ENC_H];
__device__ __nv_bfloat16 g_hh[NN * HID],      g_hl[NN * HID];
__device__ __nv_bfloat16 g_h2h[NN * DD],      g_h2l[NN * DD];
__device__ __nv_bfloat16 g_gh2[BB * DD],      g_gl2[BB * DD];   // gathered h2 rows
// transposed bf16 hi/lo weights, packed pool  (layout [N][K]); WL/WR pairs contiguous
#define WOFF_ENC1 0          // [512][64]
#define WOFF_ENC2 32768      // [64][512]
#define WOFF_W1   65536      // [512][64]  (wl1 || wr1)
#define WOFF_W2   98304      // [512][256] (wl2 || wr2)
#define WPOOL     229376
__device__ __nv_bfloat16 g_wth[WPOOL], g_wtl[WPOOL];

__device__ __forceinline__ void split_bf16(float v, __nv_bfloat16& hi, __nv_bfloat16& lo) {
    hi = __float2bfloat16(v);
    lo = __float2bfloat16(v - __bfloat162float(hi));
}

__device__ __forceinline__ uint32_t smem_u32(const void* p) {
    uint32_t a;
    asm("{ .reg .u64 t; cvta.to.shared.u64 t, %1; cvt.u32.u64 %0, t; }" : "=r"(a) : "l"(p));
    return a;
}
__device__ __forceinline__ void cp16(uint32_t d, const void* s, int sz) {
    asm volatile("cp.async.cg.shared.global [%0], [%1], 16, %2;" :: "r"(d), "l"(s), "r"(sz));
}
#define CP_COMMIT() asm volatile("cp.async.commit_group;" ::: "memory")
#define CP_WAIT(n)  asm volatile("cp.async.wait_group %0;" :: "n"(n) : "memory")

// bf16 mma.sync + ldmatrix (sm_75/80+ baseline; valid on plain sm_103 target)
__device__ __forceinline__ void mma16816(float* c, const uint32_t* a, const uint32_t* b) {
    asm volatile(
        "mma.sync.aligned.m16n8k16.row.col.f32.bf16.bf16.f32 "
        "{%0,%1,%2,%3}, {%4,%5,%6,%7}, {%8,%9}, {%0,%1,%2,%3};"
        : "+f"(c[0]), "+f"(c[1]), "+f"(c[2]), "+f"(c[3])
        : "r"(a[0]), "r"(a[1]), "r"(a[2]), "r"(a[3]), "r"(b[0]), "r"(b[1]));
}
__device__ __forceinline__ void ldsm_x4(uint32_t* r, uint32_t addr) {
    asm volatile("ldmatrix.sync.aligned.m8n8.x4.shared.b16 {%0,%1,%2,%3}, [%4];"
        : "=r"(r[0]), "=r"(r[1]), "=r"(r[2]), "=r"(r[3]) : "r"(addr));
}

#define LEAKY(v) ((v) > 0.f ? (v) : 0.2f * (v))

// ================= prep kernels ==============================================
__global__ void k_split_x(const float* __restrict__ x) {
    int i = (blockIdx.x * blockDim.x + threadIdx.x) * 4;
    if (i >= NN * HID) return;
    float4 v = *(const float4*)&x[i];
    __nv_bfloat162 h0, h1, l0, l1;
    split_bf16(v.x, h0.x, l0.x); split_bf16(v.y, h0.y, l0.y);
    split_bf16(v.z, h1.x, l1.x); split_bf16(v.w, h1.y, l1.y);
    *(__nv_bfloat162*)&g_xh[i]      = h0;
    *(__nv_bfloat162*)&g_xh[i + 2]  = h1;
    *(__nv_bfloat162*)&g_xlo[i]     = l0;
    *(__nv_bfloat162*)&g_xlo[i + 2] = l1;
}

__global__ void k_wprep(const float* __restrict__ w0, const float* __restrict__ w1,
                        const float* __restrict__ w2, const float* __restrict__ w3,
                        const float* __restrict__ w4, const float* __restrict__ w5) {
    int blk = blockIdx.x;
    const float* src; int K_, N_, dst, start;
    if      (blk < 128) { src = w0; K_ = 64;  N_ = 512; dst = WOFF_ENC1;        start = 0;   }
    else if (blk < 256) { src = w1; K_ = 512; N_ = 64;  dst = WOFF_ENC2;        start = 128; }
    else if (blk < 320) { src = w2; K_ = 64;  N_ = 256; dst = WOFF_W1;          start = 256; }
    else if (blk < 384) { src = w3; K_ = 64;  N_ = 256; dst = WOFF_W1 + 16384;  start = 320; }
    else if (blk < 640) { src = w4; K_ = 256; N_ = 256; dst = WOFF_W2;          start = 384; }
    else                { src = w5; K_ = 256; N_ = 256; dst = WOFF_W2 + 65536;  start = 640; }
    int e = (blk - start) * 256 + threadIdx.x;
    if (e >= K_ * N_) return;
    int n = e / K_, k = e % K_;
    split_bf16(src[(size_t)k * N_ + n], g_wth[dst + e], g_wtl[dst + e]);
}

__global__ void k_bprep(const float* __restrict__ bl1, const float* __restrict__ br1,
                        const float* __restrict__ bl2, const float* __restrict__ br2) {
    int t = blockIdx.x * blockDim.x + threadIdx.x;
    if (t >= 1024) return;
    if (t < 256)       g_b1[t] = bl1[t];
    else if (t < 512)  g_b1[t] = br1[t - 256];
    else if (t < 768)  g_b2[t - 512] = bl2[t - 512];
    else               g_b2[t - 512] = br2[t - 768];
}

// gather h2 hi/lo rows for the BB indexed nodes (for the small xr2 GEMM)
__global__ void k_gidx(const int* __restrict__ idx) {
    int b = blockIdx.x, t = threadIdx.x;   // 128 threads, 128 bf16x2 per row
    int n = idx[b];
    ((__nv_bfloat162*)g_gh2)[b * 128 + t] =
        ((const __nv_bfloat162*)(g_h2h + (size_t)n * DD))[t];
    ((__nv_bfloat162*)g_gl2)[b * 128 + t] =
        ((const __nv_bfloat162*)(g_h2l + (size_t)n * DD))[t];
}

// ================= CSR build ================================================
__global__ void k_zero_deg() {
    int i = blockIdx.x * blockDim.x + threadIdx.x;
    if (i < NN) g_deg[i] = 0;
}
__global__ void k_count(const int* __restrict__ EI) {
    int e = blockIdx.x * blockDim.x + threadIdx.x;
    if (e >= EP) return;
    int dst = (e < EE) ? EI[EE + e] : (e - EE);
    atomicAdd(&g_deg[dst], 1);
}
__global__ void k_scan() {
    const int CH = (NN + 1023) / 1024;
    __shared__ int part[1024];
    int t = threadIdx.x, base = t * CH, local[CH], s = 0;
#pragma unroll
    for (int i = 0; i < CH; i++) {
        int idx = base + i;
        int v = (idx < NN) ? g_deg[idx] : 0;
        local[i] = s; s += v;
    }
    part[t] = s;
    __syncthreads();
    for (int o = 1; o < 1024; o <<= 1) {
        int v = (t >= o) ? part[t - o] : 0;
        __syncthreads();
        part[t] += v;
        __syncthreads();
    }
    int ex0 = (t == 0) ? 0 : part[t - 1];
#pragma unroll
    for (int i = 0; i < CH; i++) {
        int idx = base + i;
        if (idx < NN) { int v = ex0 + local[i]; g_off[idx] = v; g_pos[idx] = v; }
    }
    if (t == 1023) g_off[NN] = ex0 + s;
}
__global__ void k_fill(const int* __restrict__ EI) {
    int e = blockIdx.x * blockDim.x + threadIdx.x;
    if (e >= EP) return;
    int dst, src;
    if (e < EE) { src = EI[e]; dst = EI[EE + e]; }
    else        { src = dst = e - EE; }
    int p = atomicAdd(&g_pos[dst], 1);
    g_src[p] = src;
}

// ================= HMMA GEMM (cp.async 2-stage pipeline + ldmatrix) ==========
#define STR 40
template <int BM, int BN, int MAXB, int ACT, int WF32, int WB16>
__global__ __launch_bounds__(256, MAXB)
void k_mma(const __nv_bfloat16* __restrict__ Ah, const __nv_bfloat16* __restrict__ Al,
           const __nv_bfloat16* __restrict__ Bh, const __nv_bfloat16* __restrict__ Bl,
           const float* __restrict__ bias, float* __restrict__ Cf,
           __nv_bfloat16* __restrict__ Ch, __nv_bfloat16* __restrict__ Cl,
           int M, int K, int Nn) {
    constexpr int WROWS = BM / 32;
    constexpr int WCOLS = 8 / WROWS;
    constexpr int WNT = BN / WCOLS;
    constexpr int NF = WNT / 8;
    constexpr int STAGE = (2 * BM + 2 * BN) * STR;
    extern __shared__ __nv_bfloat16 smem[];

    const int tid = threadIdx.x;
    const int warp = tid >> 5;
    const int lane = tid & 31;
    const int gid = lane >> 2;
    const int tid4 = lane & 3;
    const int wR = warp / WCOLS;
    const int wC = warp % WCOLS;
    const int rowBase = blockIdx.y * BM;
    const int colBase = blockIdx.x * BN;

    const int q = lane >> 3;
    const int ri = lane & 7;
    const int aRow = wR * 32 + ri + (q & 1) * 8;
    const int aCol = (q >> 1) * 8;
    const int bRow = wC * WNT + ri + (q >> 1) * 8;
    const int bCol = (q & 1) * 8;

    const uint32_t sbase = smem_u32(smem);
    constexpr int offAl = BM * STR;
    constexpr int offBh = 2 * BM * STR;
    constexpr int offBl = 2 * BM * STR + BN * STR;

    float acc[2][NF][4];
#pragma unroll
    for (int i = 0; i < 2; i++)
#pragma unroll
        for (int j = 0; j < NF; j++)
#pragma unroll
            for (int qq = 0; qq < 4; qq++) acc[i][j][qq] = 0.f;

    const int chunks = K >> 5;

    auto load_stage = [&](int st, int c) {
        __nv_bfloat16* dAh = smem + st * STAGE;
        __nv_bfloat16* dAl = dAh + BM * STR;
        __nv_bfloat16* dBh = dAl + BM * STR;
        __nv_bfloat16* dBl = dBh + BN * STR;
#pragma unroll
        for (int v = tid; v < BM * 4; v += 256) {
            int r = v >> 2, c4 = v & 3;
            int gr = rowBase + r;
            int sz = (gr < M) ? 16 : 0;
            size_t gi = (size_t)gr * K + c * 32 + c4 * 8;
            cp16(smem_u32(dAh + r * STR + c4 * 8), &Ah[gi], sz);
            cp16(smem_u32(dAl + r * STR + c4 * 8), &Al[gi], sz);
        }
#pragma unroll
        for (int v = tid; v < BN * 4; v += 256) {
            int r = v >> 2, c4 = v & 3;
            size_t gi = (size_t)(colBase + r) * K + c * 32 + c4 * 8;
            cp16(smem_u32(dBh + r * STR + c4 * 8), &Bh[gi], 16);
            cp16(smem_u32(dBl + r * STR + c4 * 8), &Bl[gi], 16);
        }
    };

    load_stage(0, 0);
    CP_COMMIT();

    for (int c = 0; c < chunks; c++) {
        if (c + 1 < chunks) {
            load_stage((c + 1) & 1, c + 1);
            CP_COMMIT();
            CP_WAIT(1);
        } else {
            CP_WAIT(0);
        }
        __syncthreads();

        const uint32_t stE = (uint32_t)((c & 1) * STAGE);
        const uint32_t aAddr = sbase + (stE + (uint32_t)(aRow * STR + aCol)) * 2;
        const uint32_t bAddr = sbase + (stE + (uint32_t)(bRow * STR + bCol)) * 2;

#pragma unroll
        for (int ks = 0; ks < 2; ks++) {
            uint32_t ah[2][4], al[2][4];
#pragma unroll
            for (int mf = 0; mf < 2; mf++) {
                uint32_t a = aAddr + (uint32_t)(mf * 16 * STR + ks * 16) * 2;
                ldsm_x4(ah[mf], a);
                ldsm_x4(al[mf], a + offAl * 2);
            }
#pragma unroll
            for (int nfp = 0; nfp < NF / 2; nfp++) {
                uint32_t bh[4], bl[4];
                uint32_t b = bAddr + (uint32_t)(nfp * 16 * STR + ks * 16) * 2;
                ldsm_x4(bh, b + offBh * 2);
                ldsm_x4(bl, b + offBl * 2);
#pragma unroll
                for (int j = 0; j < 2; j++) {
                    int nf = nfp * 2 + j;
#pragma unroll
                    for (int mf = 0; mf < 2; mf++) {
                        mma16816(acc[mf][nf], ah[mf], &bh[2 * j]);
                        mma16816(acc[mf][nf], ah[mf], &bl[2 * j]);
                        mma16816(acc[mf][nf], al[mf], &bh[2 * j]);
                    }
                }
            }
        }
        __syncthreads();
    }

    // epilogue: bias + act (+ bf16 split), straight from fragments
#pragma unroll
    for (int nf = 0; nf < NF; nf++) {
        int col = colBase + wC * WNT + nf * 8 + tid4 * 2;
        float b0 = bias[col], b1 = bias[col + 1];
#pragma unroll
        for (int mf = 0; mf < 2; mf++) {
#pragma unroll
            for (int half = 0; half < 2; half++) {
                int row = rowBase + wR * 32 + mf * 16 + gid + half * 8;
                if (row >= M) continue;
                float v0 = acc[mf][nf][half * 2] + b0;
                float v1 = acc[mf][nf][half * 2 + 1] + b1;
                if (ACT == 1) { v0 = fmaxf(v0, 0.f); v1 = fmaxf(v1, 0.f); }
                size_t oi = (size_t)row * Nn + col;
                if (WF32) *(float2*)&Cf[oi] = make_float2(v0, v1);
                if (WB16) {
                    __nv_bfloat162 hh2, ll2;
                    split_bf16(v0, hh2.x, ll2.x);
                    split_bf16(v1, hh2.y, ll2.y);
                    *(__nv_bfloat162*)&Ch[oi] = hh2;
                    *(__nv_bfloat162*)&Cl[oi] = ll2;
                }
            }
        }
    }
}

// ================= fused GATv2 layer 1 (4-edge unrolled, proven form) ========
// xlr: [NN][512], xl = cols 0..255, xr = cols 256..511
__global__ __launch_bounds__(128, 8)
void k_gat(const float* __restrict__ xlr,
           const float* __restrict__ att, const float* __restrict__ bias,
           __nv_bfloat16* outH, __nv_bfloat16* outL) {
    const int i = blockIdx.x;
    const int w = threadIdx.x >> 5;
    const int lane = threadIdx.x & 31;
    const int f = w * HID + lane * 2;
    const int s0 = g_off[i], s1 = g_off[i + 1];   // s1 > s0 (self loop)

    const float2 xrv = *(const float2*)(xlr + (size_t)i * 512 + 256 + f);
    const float2 atv = *(const float2*)(att + f);

    float acc0 = 0.f, acc1 = 0.f, den = 0.f;
    int p = s0;
    for (; p + 4 <= s1; p += 4) {
        int sA = __ldg(&g_src[p]);
        int sB = __ldg(&g_src[p + 1]);
        int sC = __ldg(&g_src[p + 2]);
        int sD = __ldg(&g_src[p + 3]);
        float2 xvA = *(const float2*)(xlr + (size_t)sA * 512 + f);
        float2 xvB = *(const float2*)(xlr + (size_t)sB * 512 + f);
        float2 xvC = *(const float2*)(xlr + (size_t)sC * 512 + f);
        float2 xvD = *(const float2*)(xlr + (size_t)sD * 512 + f);
        float sa = LEAKY(xvA.x + xrv.x) * atv.x + LEAKY(xvA.y + xrv.y) * atv.y;
        float sb = LEAKY(xvB.x + xrv.x) * atv.x + LEAKY(xvB.y + xrv.y) * atv.y;
        float sc = LEAKY(xvC.x + xrv.x) * atv.x + LEAKY(xvC.y + xrv.y) * atv.y;
        float sd = LEAKY(xvD.x + xrv.x) * atv.x + LEAKY(xvD.y + xrv.y) * atv.y;
#pragma unroll
        for (int o = 16; o; o >>= 1) {
            sa += __shfl_xor_sync(0xffffffffu, sa, o);
            sb += __shfl_xor_sync(0xffffffffu, sb, o);
            sc += __shfl_xor_sync(0xffffffffu, sc, o);
            sd += __shfl_xor_sync(0xffffffffu, sd, o);
        }
        float exa = __expf(sa), exb = __expf(sb);
        float exc = __expf(sc), exd = __expf(sd);
        acc0 += exa * xvA.x + exb * xvB.x + exc * xvC.x + exd * xvD.x;
        acc1 += exa * xvA.y + exb * xvB.y + exc * xvC.y + exd * xvD.y;
        den  += exa + exb + exc + exd;
    }
    for (; p < s1; p++) {
        int sA = __ldg(&g_src[p]);
        float2 xvA = *(const float2*)(xlr + (size_t)sA * 512 + f);
        float sa = LEAKY(xvA.x + xrv.x) * atv.x + LEAKY(xvA.y + xrv.y) * atv.y;
#pragma unroll
        for (int o = 16; o; o >>= 1) sa += __shfl_xor_sync(0xffffffffu, sa, o);
        float exa = __expf(sa);
        acc0 += exa * xvA.x; acc1 += exa * xvA.y; den += exa;
    }
    float rr = 1.f / (den + 1e-16f);
    float o0 = fmaxf(acc0 * rr + bias[f], 0.f);
    float o1 = fmaxf(acc1 * rr + bias[f + 1], 0.f);
    size_t oi = (size_t)i * DD + f;
    __nv_bfloat162 h, l;
    split_bf16(o0, h.x, l.x); split_bf16(o1, h.y, l.y);
    *(__nv_bfloat162*)&outH[oi] = h;
    *(__nv_bfloat162*)&outL[oi] = l;
}

// ================= GATv2 layer 2: only the BB indexed nodes ==================
// xl2: [NN][256]; xr2, out: compact [BB][256]
__global__ __launch_bounds__(128, 8)
void k_gat2(const int* __restrict__ idx,
            const float* __restrict__ xl2, const float* __restrict__ xr2,
            const float* __restrict__ att, const float* __restrict__ bias,
            float* __restrict__ outc) {
    const int b = blockIdx.x;
    const int node = idx[b];
    const int w = threadIdx.x >> 5;
    const int lane = threadIdx.x & 31;
    const int f = w * HID + lane * 2;
    const int s0 = g_off[node], s1 = g_off[node + 1];

    const float2 xrv = *(const float2*)(xr2 + (size_t)b * DD + f);
    const float2 atv = *(const float2*)(att + f);

    float acc0 = 0.f, acc1 = 0.f, den = 0.f;
    int p = s0;
    for (; p + 4 <= s1; p += 4) {
        int sA = __ldg(&g_src[p]);
        int sB = __ldg(&g_src[p + 1]);
        int sC = __ldg(&g_src[p + 2]);
        int sD = __ldg(&g_src[p + 3]);
        float2 xvA = *(const float2*)(xl2 + (size_t)sA * DD + f);
        float2 xvB = *(const float2*)(xl2 + (size_t)sB * DD + f);
        float2 xvC = *(const float2*)(xl2 + (size_t)sC * DD + f);
        float2 xvD = *(const float2*)(xl2 + (size_t)sD * DD + f);
        float sa = LEAKY(xvA.x + xrv.x) * atv.x + LEAKY(xvA.y + xrv.y) * atv.y;
        float sb = LEAKY(xvB.x + xrv.x) * atv.x + LEAKY(xvB.y + xrv.y) * atv.y;
        float sc = LEAKY(xvC.x + xrv.x) * atv.x + LEAKY(xvC.y + xrv.y) * atv.y;
        float sd = LEAKY(xvD.x + xrv.x) * atv.x + LEAKY(xvD.y + xrv.y) * atv.y;
#pragma unroll
        for (int o = 16; o; o >>= 1) {
            sa += __shfl_xor_sync(0xffffffffu, sa, o);
            sb += __shfl_xor_sync(0xffffffffu, sb, o);
            sc += __shfl_xor_sync(0xffffffffu, sc, o);
            sd += __shfl_xor_sync(0xffffffffu, sd, o);
        }
        float exa = __expf(sa), exb = __expf(sb);
        float exc = __expf(sc), exd = __expf(sd);
        acc0 += exa * xvA.x + exb * xvB.x + exc * xvC.x + exd * xvD.x;
        acc1 += exa * xvA.y + exb * xvB.y + exc * xvC.y + exd * xvD.y;
        den  += exa + exb + exc + exd;
    }
    for (; p < s1; p++) {
        int sA = __ldg(&g_src[p]);
        float2 xvA = *(const float2*)(xl2 + (size_t)sA * DD + f);
        float sa = LEAKY(xvA.x + xrv.x) * atv.x + LEAKY(xvA.y + xrv.y) * atv.y;
#pragma unroll
        for (int o = 16; o; o >>= 1) sa += __shfl_xor_sync(0xffffffffu, sa, o);
        float exa = __expf(sa);
        acc0 += exa * xvA.x; acc1 += exa * xvA.y; den += exa;
    }
    float rr = 1.f / (den + 1e-16f);
    size_t oi = (size_t)b * DD + f;
    outc[oi]     = fmaxf(acc0 * rr + bias[f], 0.f);
    outc[oi + 1] = fmaxf(acc1 * rr + bias[f + 1], 0.f);
}

// ================= dueling head (compact h3 by batch slot) ===================
__global__ void k_head(const int* __restrict__ idx,
                       const float* __restrict__ h3c,
                       const float* __restrict__ qw1, const float* __restrict__ qb1,
                       const float* __restrict__ qw2, const float* __restrict__ qb2,
                       const float* __restrict__ vw1, const float* __restrict__ vb1,
                       const float* __restrict__ vw2, const float* __restrict__ vb2,
                       float* __restrict__ out) {
    __shared__ float f[CAT];
    __shared__ float r0[DUEL_H], r1[DUEL_H], r2[DUEL_H];
    int b = blockIdx.x, t = threadIdx.x;
    int n = idx[b];
    for (int i = t; i < CAT; i += DUEL_H) {
        float v;
        if (i < HID)
            v = __bfloat162float(g_hh[(size_t)n * HID + i]) +
                __bfloat162float(g_hl[(size_t)n * HID + i]);
        else if (i < HID + DD)
            v = __bfloat162float(g_h2h[(size_t)n * DD + (i - HID)]) +
                __bfloat162float(g_h2l[(size_t)n * DD + (i - HID)]);
        else
            v = h3c[(size_t)b * DD + (i - HID - DD)];
        f[i] = v;
    }
    __syncthreads();
    float q = 0.f, v = 0.f;
#pragma unroll 4
    for (int k = 0; k < CAT; k++) {
        float fv = f[k];
        q += fv * qw1[(size_t)k * DUEL_H + t];
        v += fv * vw1[(size_t)k * DUEL_H + t];
    }
    q = fmaxf(q + qb1[t], 0.f);
    v = fmaxf(v + vb1[t], 0.f);
    r0[t] = q * qw2[t * 2 + 0];
    r1[t] = q * qw2[t * 2 + 1];
    r2[t] = v * vw2[t];
    __syncthreads();
    for (int o = 64; o; o >>= 1) {
        if (t < o) { r0[t] += r0[t + o]; r1[t] += r1[t + o]; r2[t] += r2[t + o]; }
        __syncthreads();
    }
    if (t == 0) {
        float q0 = r0[0] + qb2[0], q1 = r1[0] + qb2[1], vv = r2[0] + vb2[0];
        float m = 0.5f * (q0 + q1);
        out[b * 2 + 0] = q0 - m + vv;
        out[b * 2 + 1] = q1 - m + vv;
    }
}

// ================= launch ====================================================
extern "C" void kernel_launch(void* const* d_in, const int* in_sizes, int n_in,
                              void* d_out, int out_size) {
    const float* x      = (const float*)d_in[0];
    const int*   EI     = (const int*)  d_in[1];
    const int*   idx    = (const int*)  d_in[2];
    const float* enc_w1 = (const float*)d_in[3];
    const float* enc_b1 = (const float*)d_in[4];
    const float* enc_w2 = (const float*)d_in[5];
    const float* enc_b2 = (const float*)d_in[6];
    const float* wl1    = (const float*)d_in[7];
    const float* bl1    = (const float*)d_in[8];
    const float* wr1    = (const float*)d_in[9];
    const float* br1    = (const float*)d_in[10];
    const float* att1   = (const float*)d_in[11];
    const float* bias1  = (const float*)d_in[12];
    const float* wl2    = (const float*)d_in[13];
    const float* bl2    = (const float*)d_in[14];
    const float* wr2    = (const float*)d_in[15];
    const float* br2    = (const float*)d_in[16];
    const float* att2   = (const float*)d_in[17];
    const float* bias2  = (const float*)d_in[18];
    const float* q_w1   = (const float*)d_in[19];
    const float* q_b1   = (const float*)d_in[20];
    const float* q_w2   = (const float*)d_in[21];
    const float* q_b2   = (const float*)d_in[22];
    const float* v_w1   = (const float*)d_in[23];
    const float* v_b1   = (const float*)d_in[24];
    const float* v_w2   = (const float*)d_in[25];
    const float* v_b2   = (const float*)d_in[26];
    float* out = (float*)d_out;

    float *xlr, *xl2, *xr2, *h3, *b1, *b2;
    __nv_bfloat16 *xh, *xlo, *h512h, *h512l, *hh, *hl, *h2h, *h2l, *gh2, *gl2, *wth, *wtl;
    cudaGetSymbolAddress((void**)&xlr,  g_xlr);
    cudaGetSymbolAddress((void**)&xl2,  g_xl2);
    cudaGetSymbolAddress((void**)&xr2,  g_xr2);
    cudaGetSymbolAddress((void**)&h3,   g_h3);
    cudaGetSymbolAddress((void**)&b1,   g_b1);
    cudaGetSymbolAddress((void**)&b2,   g_b2);
    cudaGetSymbolAddress((void**)&xh,   g_xh);
    cudaGetSymbolAddress((void**)&xlo,  g_xlo);
    cudaGetSymbolAddress((void**)&h512h, g_h512h);
    cudaGetSymbolAddress((void**)&h512l, g_h512l);
    cudaGetSymbolAddress((void**)&hh,   g_hh);
    cudaGetSymbolAddress((void**)&hl,   g_hl);
    cudaGetSymbolAddress((void**)&h2h,  g_h2h);
    cudaGetSymbolAddress((void**)&h2l,  g_h2l);
    cudaGetSymbolAddress((void**)&gh2,  g_gh2);
    cudaGetSymbolAddress((void**)&gl2,  g_gl2);
    cudaGetSymbolAddress((void**)&wth,  g_wth);
    cudaGetSymbolAddress((void**)&wtl,  g_wtl);

    // Lazy one-time host resources for fork/join (graph-capture legal)
    static cudaStream_t s2 = nullptr, s3 = nullptr;
    static cudaEvent_t evFork = nullptr, evJoin = nullptr, evPrep = nullptr;
    static cudaEvent_t evG = nullptr, evXr = nullptr;
    if (!s2) {
        cudaStreamCreateWithFlags(&s2, cudaStreamNonBlocking);
        cudaStreamCreateWithFlags(&s3, cudaStreamNonBlocking);
        cudaEventCreateWithFlags(&evFork, cudaEventDisableTiming);
        cudaEventCreateWithFlags(&evJoin, cudaEventDisableTiming);
        cudaEventCreateWithFlags(&evPrep, cudaEventDisableTiming);
        cudaEventCreateWithFlags(&evG, cudaEventDisableTiming);
        cudaEventCreateWithFlags(&evXr, cudaEventDisableTiming);
    }

    const int SM_64_64 = 2 * (2 * 64 + 2 * 64) * STR * 2;     // 40,960 B
    cudaFuncSetAttribute((const void*)k_mma<64, 64, 3, 1, 0, 1>, cudaFuncAttributeMaxDynamicSharedMemorySize, SM_64_64);
    cudaFuncSetAttribute((const void*)k_mma<64, 64, 3, 0, 1, 0>, cudaFuncAttributeMaxDynamicSharedMemorySize, SM_64_64);

    const int MT64 = (NN + 63) / 64;     // 313

    // ---- fork: CSR build chain on s2; weight prep on s3 ----
    cudaEventRecord(evFork, 0);
    cudaStreamWaitEvent(s2, evFork, 0);
    cudaStreamWaitEvent(s3, evFork, 0);
    k_zero_deg<<<(NN + 255) / 256, 256, 0, s2>>>();
    k_count<<<(EP + 255) / 256, 256, 0, s2>>>(EI);
    k_scan<<<1, 1024, 0, s2>>>();
    k_fill<<<(EP + 255) / 256, 256, 0, s2>>>(EI);
    cudaEventRecord(evJoin, s2);

    k_wprep<<<896, 256, 0, s3>>>(enc_w1, enc_w2, wl1, wr1, wl2, wr2);
    k_bprep<<<4, 256, 0, s3>>>(bl1, br1, bl2, br2);
    cudaEventRecord(evPrep, s3);

    // ---- main stream: activation split, then GEMM chain ----
    k_split_x<<<(NN * HID / 4 + 255) / 256, 256>>>(x);
    cudaStreamWaitEvent(0, evPrep, 0);

    // enc1: [NN,64] @ [64,512] -> h512 (bf16 hi/lo), relu
    k_mma<64, 64, 3, 1, 0, 1><<<dim3(ENC_H / 64, MT64), 256, SM_64_64>>>(
        xh, xlo, wth + WOFF_ENC1, wtl + WOFF_ENC1, enc_b1, nullptr, h512h, h512l, NN, 64, ENC_H);
    // enc2: [NN,512] @ [512,64] -> h (bf16 hi/lo only), relu
    k_mma<64, 64, 3, 1, 0, 1><<<dim3(1, MT64), 256, SM_64_64>>>(
        h512h, h512l, wth + WOFF_ENC2, wtl + WOFF_ENC2, enc_b2, nullptr, hh, hl, NN, ENC_H, HID);

    // conv1: combined [xl|xr] transform, N=512, K=64
    k_mma<64, 64, 3, 0, 1, 0><<<dim3(8, MT64), 256, SM_64_64>>>(
        hh, hl, wth + WOFF_W1, wtl + WOFF_W1, b1, xlr, nullptr, nullptr, NN, HID, 512);

    // ---- join: CSR must be ready before gat1 ----
    cudaStreamWaitEvent(0, evJoin, 0);
    k_gat<<<NN, 128>>>(xlr, att1, bias1, h2h, h2l);
    cudaEventRecord(evG, 0);

    // side stream: gather indexed h2 rows, small xr2 GEMM (M=128, K=256, N=256)
    cudaStreamWaitEvent(s2, evG, 0);
    k_gidx<<<BB, 128, 0, s2>>>(idx);
    k_mma<64, 64, 3, 0, 1, 0><<<dim3(4, 2), 256, SM_64_64, s2>>>(
        gh2, gl2, wth + WOFF_W2 + 65536, wtl + WOFF_W2 + 65536, b2 + 256,
        xr2, nullptr, nullptr, BB, DD, DD);
    cudaEventRecord(evXr, s2);

    // main: conv2 xl-only transform, N=256, K=256, all nodes
    k_mma<64, 64, 3, 0, 1, 0><<<dim3(4, MT64), 256, SM_64_64>>>(
        h2h, h2l, wth + WOFF_W2, wtl + WOFF_W2, b2, xl2, nullptr, nullptr, NN, DD, DD);

    // gat2 over the 128 indexed nodes only
    cudaStreamWaitEvent(0, evXr, 0);
    k_gat2<<<BB, 128>>>(idx, xl2, xr2, att2, bias2, h3);

    // heads
    k_head<<<BB, DUEL_H>>>(idx, h3,
                           q_w1, q_b1, q_w2, q_b2, v_w1, v_b1, v_w2, v_b2, out);
}

// round 17
// speedup vs baseline: 1.6094x; 1.2443x over previous
#include <cuda_runtime.h>
#include <cuda_bf16.h>
#include <cstdint>

// Problem constants
#define NN 20000
#define EE 320000
#define EP (EE + NN)          // 340000
#define BB 128
#define HID 64
#define HEADS 4
#define DD 256
#define CAT 576
#define ENC_H 512
#define DUEL_H 128

// ================= scratch (static device memory) ============================
__device__ float g_xlr[NN * 512];     // conv1: [xl | xr] per row
__device__ float g_xl2[NN * DD];      // conv2: xl transform, compact over S1
__device__ float g_xr2[BB * DD];      // conv2: xr transform, indexed nodes only
__device__ float g_h3[BB * DD];       // gat2 output, compact over indexed nodes
__device__ float g_b1[512], g_b2[512];  // pooled conv biases [bl | br]
__device__ int   g_deg[NN];
__device__ int   g_off[NN + 1];
__device__ int   g_pos[NN];
__device__ int   g_src[EP];           // CSR payload: source node id (direct)
__device__ int   g_need[NN];          // S1 membership flag
__device__ int   g_slot[NN];          // node -> compact slot
__device__ int   g_list[NN];          // compact slot -> node
__device__ int   g_cnt;               // |S1|
// bf16 hi/lo activations
__device__ __nv_bfloat16 g_xh[NN * HID],      g_xlo[NN * HID];
__device__ __nv_bfloat16 g_h512h[NN * ENC_H], g_h512l[NN * ENC_H];
__device__ __nv_bfloat16 g_hh[NN * HID],      g_hl[NN * HID];
__device__ __nv_bfloat16 g_h2h[NN * DD],      g_h2l[NN * DD];
__device__ __nv_bfloat16 g_ch2h[NN * DD],     g_ch2l[NN * DD];  // compact h2 rows (S1)
__device__ __nv_bfloat16 g_gh2[BB * DD],      g_gl2[BB * DD];   // gathered h2 rows (idx)
// transposed bf16 hi/lo weights, packed pool  (layout [N][K]); WL/WR pairs contiguous
#define WOFF_ENC1 0          // [512][64]
#define WOFF_ENC2 32768      // [64][512]
#define WOFF_W1   65536      // [512][64]  (wl1 || wr1)
#define WOFF_W2   98304      // [512][256] (wl2 || wr2)
#define WPOOL     229376
__device__ __nv_bfloat16 g_wth[WPOOL], g_wtl[WPOOL];

__device__ __forceinline__ void split_bf16(float v, __nv_bfloat16& hi, __nv_bfloat16& lo) {
    hi = __float2bfloat16(v);
    lo = __float2bfloat16(v - __bfloat162float(hi));
}

__device__ __forceinline__ uint32_t smem_u32(const void* p) {
    uint32_t a;
    asm("{ .reg .u64 t; cvta.to.shared.u64 t, %1; cvt.u32.u64 %0, t; }" : "=r"(a) : "l"(p));
    return a;
}
__device__ __forceinline__ void cp16(uint32_t d, const void* s, int sz) {
    asm volatile("cp.async.cg.shared.global [%0], [%1], 16, %2;" :: "r"(d), "l"(s), "r"(sz));
}
#define CP_COMMIT() asm volatile("cp.async.commit_group;" ::: "memory")
#define CP_WAIT(n)  asm volatile("cp.async.wait_group %0;" :: "n"(n) : "memory")

// bf16 mma.sync + ldmatrix (sm_75/80+ baseline; valid on plain sm_103 target)
__device__ __forceinline__ void mma16816(float* c, const uint32_t* a, const uint32_t* b) {
    asm volatile(
        "mma.sync.aligned.m16n8k16.row.col.f32.bf16.bf16.f32 "
        "{%0,%1,%2,%3}, {%4,%5,%6,%7}, {%8,%9}, {%0,%1,%2,%3};"
        : "+f"(c[0]), "+f"(c[1]), "+f"(c[2]), "+f"(c[3])
        : "r"(a[0]), "r"(a[1]), "r"(a[2]), "r"(a[3]), "r"(b[0]), "r"(b[1]));
}
__device__ __forceinline__ void ldsm_x4(uint32_t* r, uint32_t addr) {
    asm volatile("ldmatrix.sync.aligned.m8n8.x4.shared.b16 {%0,%1,%2,%3}, [%4];"
        : "=r"(r[0]), "=r"(r[1]), "=r"(r[2]), "=r"(r[3]) : "r"(addr));
}

#define LEAKY(v) ((v) > 0.f ? (v) : 0.2f * (v))

// ================= prep kernels ==============================================
__global__ void k_split_x(const float* __restrict__ x) {
    int i = (blockIdx.x * blockDim.x + threadIdx.x) * 4;
    if (i >= NN * HID) return;
    float4 v = *(const float4*)&x[i];
    __nv_bfloat162 h0, h1, l0, l1;
    split_bf16(v.x, h0.x, l0.x); split_bf16(v.y, h0.y, l0.y);
    split_bf16(v.z, h1.x, l1.x); split_bf16(v.w, h1.y, l1.y);
    *(__nv_bfloat162*)&g_xh[i]      = h0;
    *(__nv_bfloat162*)&g_xh[i + 2]  = h1;
    *(__nv_bfloat162*)&g_xlo[i]     = l0;
    *(__nv_bfloat162*)&g_xlo[i + 2] = l1;
}

__global__ void k_wprep(const float* __restrict__ w0, const float* __restrict__ w1,
                        const float* __restrict__ w2, const float* __restrict__ w3,
                        const float* __restrict__ w4, const float* __restrict__ w5) {
    int blk = blockIdx.x;
    const float* src; int K_, N_, dst, start;
    if      (blk < 128) { src = w0; K_ = 64;  N_ = 512; dst = WOFF_ENC1;        start = 0;   }
    else if (blk < 256) { src = w1; K_ = 512; N_ = 64;  dst = WOFF_ENC2;        start = 128; }
    else if (blk < 320) { src = w2; K_ = 64;  N_ = 256; dst = WOFF_W1;          start = 256; }
    else if (blk < 384) { src = w3; K_ = 64;  N_ = 256; dst = WOFF_W1 + 16384;  start = 320; }
    else if (blk < 640) { src = w4; K_ = 256; N_ = 256; dst = WOFF_W2;          start = 384; }
    else                { src = w5; K_ = 256; N_ = 256; dst = WOFF_W2 + 65536;  start = 640; }
    int e = (blk - start) * 256 + threadIdx.x;
    if (e >= K_ * N_) return;
    int n = e / K_, k = e % K_;
    split_bf16(src[(size_t)k * N_ + n], g_wth[dst + e], g_wtl[dst + e]);
}

__global__ void k_bprep(const float* __restrict__ bl1, const float* __restrict__ br1,
                        const float* __restrict__ bl2, const float* __restrict__ br2) {
    int t = blockIdx.x * blockDim.x + threadIdx.x;
    if (t >= 1024) return;
    if (t < 256)       g_b1[t] = bl1[t];
    else if (t < 512)  g_b1[t] = br1[t - 256];
    else if (t < 768)  g_b2[t - 512] = bl2[t - 512];
    else               g_b2[t - 512] = br2[t - 768];
}

// gather h2 hi/lo rows for the BB indexed nodes (for the small xr2 GEMM)
__global__ void k_gidx(const int* __restrict__ idx) {
    int b = blockIdx.x, t = threadIdx.x;   // 128 threads, 128 bf16x2 per row
    int n = idx[b];
    ((__nv_bfloat162*)g_gh2)[b * 128 + t] =
        ((const __nv_bfloat162*)(g_h2h + (size_t)n * DD))[t];
    ((__nv_bfloat162*)g_gl2)[b * 128 + t] =
        ((const __nv_bfloat162*)(g_h2l + (size_t)n * DD))[t];
}

// gather compact h2 rows for S1 (conv2-xl input)
__global__ void k_gath2() {
    int b = blockIdx.x;
    if (b >= g_cnt) return;
    int n = g_list[b];
    int t = threadIdx.x;   // 128
    ((__nv_bfloat162*)g_ch2h)[b * 128 + t] =
        ((const __nv_bfloat162*)(g_h2h + (size_t)n * DD))[t];
    ((__nv_bfloat162*)g_ch2l)[b * 128 + t] =
        ((const __nv_bfloat162*)(g_h2l + (size_t)n * DD))[t];
}

// ================= CSR build + S1 slice ======================================
__global__ void k_zero_deg() {
    int i = blockIdx.x * blockDim.x + threadIdx.x;
    if (i < NN) { g_deg[i] = 0; g_need[i] = 0; }
}
__global__ void k_count(const int* __restrict__ EI) {
    int e = blockIdx.x * blockDim.x + threadIdx.x;
    if (e >= EP) return;
    int dst = (e < EE) ? EI[EE + e] : (e - EE);
    atomicAdd(&g_deg[dst], 1);
}
__global__ void k_scan() {
    const int CH = (NN + 1023) / 1024;
    __shared__ int part[1024];
    int t = threadIdx.x, base = t * CH, local[CH], s = 0;
#pragma unroll
    for (int i = 0; i < CH; i++) {
        int idx = base + i;
        int v = (idx < NN) ? g_deg[idx] : 0;
        local[i] = s; s += v;
    }
    part[t] = s;
    __syncthreads();
    for (int o = 1; o < 1024; o <<= 1) {
        int v = (t >= o) ? part[t - o] : 0;
        __syncthreads();
        part[t] += v;
        __syncthreads();
    }
    int ex0 = (t == 0) ? 0 : part[t - 1];
#pragma unroll
    for (int i = 0; i < CH; i++) {
        int idx = base + i;
        if (idx < NN) { int v = ex0 + local[i]; g_off[idx] = v; g_pos[idx] = v; }
    }
    if (t == 1023) g_off[NN] = ex0 + s;
}
__global__ void k_fill(const int* __restrict__ EI) {
    int e = blockIdx.x * blockDim.x + threadIdx.x;
    if (e >= EP) return;
    int dst, src;
    if (e < EE) { src = EI[e]; dst = EI[EE + e]; }
    else        { src = dst = e - EE; }
    int p = atomicAdd(&g_pos[dst], 1);
    g_src[p] = src;
}
// mark S1 = sources of edges incident to indexed nodes (self-loops cover idx)
__global__ void k_mark(const int* __restrict__ idx) {
    int b = blockIdx.x;         // BB blocks
    int n = idx[b];
    int s0 = g_off[n], s1 = g_off[n + 1];
    for (int p = s0 + threadIdx.x; p < s1; p += blockDim.x)
        g_need[g_src[p]] = 1;
}
// compact S1: slot/list/cnt (single block scan)
__global__ void k_compact() {
    const int CH = (NN + 1023) / 1024;
    __shared__ int part[1024];
    int t = threadIdx.x, base = t * CH, local[CH], s = 0;
#pragma unroll
    for (int i = 0; i < CH; i++) {
        int idx = base + i;
        int v = (idx < NN) ? g_need[idx] : 0;
        local[i] = s; s += v;
    }
    part[t] = s;
    __syncthreads();
    for (int o = 1; o < 1024; o <<= 1) {
        int v = (t >= o) ? part[t - o] : 0;
        __syncthreads();
        part[t] += v;
        __syncthreads();
    }
    int ex0 = (t == 0) ? 0 : part[t - 1];
#pragma unroll
    for (int i = 0; i < CH; i++) {
        int idx = base + i;
        if (idx < NN && g_need[idx]) {
            int slot = ex0 + local[i];
            g_slot[idx] = slot;
            g_list[slot] = idx;
        }
    }
    if (t == 1023) g_cnt = ex0 + s;
}

// ================= HMMA GEMM (cp.async 2-stage pipeline + ldmatrix) ==========
// Mdyn: optional device pointer overriding M (blocks beyond it exit early).
#define STR 40
template <int BM, int BN, int MAXB, int ACT, int WF32, int WB16>
__global__ __launch_bounds__(256, MAXB)
void k_mma(const __nv_bfloat16* __restrict__ Ah, const __nv_bfloat16* __restrict__ Al,
           const __nv_bfloat16* __restrict__ Bh, const __nv_bfloat16* __restrict__ Bl,
           const float* __restrict__ bias, float* __restrict__ Cf,
           __nv_bfloat16* __restrict__ Ch, __nv_bfloat16* __restrict__ Cl,
           int M, int K, int Nn, const int* Mdyn) {
    constexpr int WROWS = BM / 32;
    constexpr int WCOLS = 8 / WROWS;
    constexpr int WNT = BN / WCOLS;
    constexpr int NF = WNT / 8;
    constexpr int STAGE = (2 * BM + 2 * BN) * STR;
    extern __shared__ __nv_bfloat16 smem[];

    const int rowBase = blockIdx.y * BM;
    if (Mdyn) { M = *Mdyn; if (rowBase >= M) return; }

    const int tid = threadIdx.x;
    const int warp = tid >> 5;
    const int lane = tid & 31;
    const int gid = lane >> 2;
    const int tid4 = lane & 3;
    const int wR = warp / WCOLS;
    const int wC = warp % WCOLS;
    const int colBase = blockIdx.x * BN;

    const int q = lane >> 3;
    const int ri = lane & 7;
    const int aRow = wR * 32 + ri + (q & 1) * 8;
    const int aCol = (q >> 1) * 8;
    const int bRow = wC * WNT + ri + (q >> 1) * 8;
    const int bCol = (q & 1) * 8;

    const uint32_t sbase = smem_u32(smem);
    constexpr int offAl = BM * STR;
    constexpr int offBh = 2 * BM * STR;
    constexpr int offBl = 2 * BM * STR + BN * STR;

    float acc[2][NF][4];
#pragma unroll
    for (int i = 0; i < 2; i++)
#pragma unroll
        for (int j = 0; j < NF; j++)
#pragma unroll
            for (int qq = 0; qq < 4; qq++) acc[i][j][qq] = 0.f;

    const int chunks = K >> 5;

    auto load_stage = [&](int st, int c) {
        __nv_bfloat16* dAh = smem + st * STAGE;
        __nv_bfloat16* dAl = dAh + BM * STR;
        __nv_bfloat16* dBh = dAl + BM * STR;
        __nv_bfloat16* dBl = dBh + BN * STR;
#pragma unroll
        for (int v = tid; v < BM * 4; v += 256) {
            int r = v >> 2, c4 = v & 3;
            int gr = rowBase + r;
            int sz = (gr < M) ? 16 : 0;
            size_t gi = (size_t)gr * K + c * 32 + c4 * 8;
            cp16(smem_u32(dAh + r * STR + c4 * 8), &Ah[gi], sz);
            cp16(smem_u32(dAl + r * STR + c4 * 8), &Al[gi], sz);
        }
#pragma unroll
        for (int v = tid; v < BN * 4; v += 256) {
            int r = v >> 2, c4 = v & 3;
            size_t gi = (size_t)(colBase + r) * K + c * 32 + c4 * 8;
            cp16(smem_u32(dBh + r * STR + c4 * 8), &Bh[gi], 16);
            cp16(smem_u32(dBl + r * STR + c4 * 8), &Bl[gi], 16);
        }
    };

    load_stage(0, 0);
    CP_COMMIT();

    for (int c = 0; c < chunks; c++) {
        if (c + 1 < chunks) {
            load_stage((c + 1) & 1, c + 1);
            CP_COMMIT();
            CP_WAIT(1);
        } else {
            CP_WAIT(0);
        }
        __syncthreads();

        const uint32_t stE = (uint32_t)((c & 1) * STAGE);
        const uint32_t aAddr = sbase + (stE + (uint32_t)(aRow * STR + aCol)) * 2;
        const uint32_t bAddr = sbase + (stE + (uint32_t)(bRow * STR + bCol)) * 2;

#pragma unroll
        for (int ks = 0; ks < 2; ks++) {
            uint32_t ah[2][4], al[2][4];
#pragma unroll
            for (int mf = 0; mf < 2; mf++) {
                uint32_t a = aAddr + (uint32_t)(mf * 16 * STR + ks * 16) * 2;
                ldsm_x4(ah[mf], a);
                ldsm_x4(al[mf], a + offAl * 2);
            }
#pragma unroll
            for (int nfp = 0; nfp < NF / 2; nfp++) {
                uint32_t bh[4], bl[4];
                uint32_t b = bAddr + (uint32_t)(nfp * 16 * STR + ks * 16) * 2;
                ldsm_x4(bh, b + offBh * 2);
                ldsm_x4(bl, b + offBl * 2);
#pragma unroll
                for (int j = 0; j < 2; j++) {
                    int nf = nfp * 2 + j;
#pragma unroll
                    for (int mf = 0; mf < 2; mf++) {
                        mma16816(acc[mf][nf], ah[mf], &bh[2 * j]);
                        mma16816(acc[mf][nf], ah[mf], &bl[2 * j]);
                        mma16816(acc[mf][nf], al[mf], &bh[2 * j]);
                    }
                }
            }
        }
        __syncthreads();
    }

    // epilogue: bias + act (+ bf16 split), straight from fragments
#pragma unroll
    for (int nf = 0; nf < NF; nf++) {
        int col = colBase + wC * WNT + nf * 8 + tid4 * 2;
        float b0 = bias[col], b1 = bias[col + 1];
#pragma unroll
        for (int mf = 0; mf < 2; mf++) {
#pragma unroll
            for (int half = 0; half < 2; half++) {
                int row = rowBase + wR * 32 + mf * 16 + gid + half * 8;
                if (row >= M) continue;
                float v0 = acc[mf][nf][half * 2] + b0;
                float v1 = acc[mf][nf][half * 2 + 1] + b1;
                if (ACT == 1) { v0 = fmaxf(v0, 0.f); v1 = fmaxf(v1, 0.f); }
                size_t oi = (size_t)row * Nn + col;
                if (WF32) *(float2*)&Cf[oi] = make_float2(v0, v1);
                if (WB16) {
                    __nv_bfloat162 hh2, ll2;
                    split_bf16(v0, hh2.x, ll2.x);
                    split_bf16(v1, hh2.y, ll2.y);
                    *(__nv_bfloat162*)&Ch[oi] = hh2;
                    *(__nv_bfloat162*)&Cl[oi] = ll2;
                }
            }
        }
    }
}

// ================= fused GATv2 layer 1 (4-edge unrolled, S1 only) ============
// xlr: [NN][512], xl = cols 0..255, xr = cols 256..511
__global__ __launch_bounds__(128, 8)
void k_gat(const float* __restrict__ xlr,
           const float* __restrict__ att, const float* __restrict__ bias,
           __nv_bfloat16* outH, __nv_bfloat16* outL) {
    const int i = blockIdx.x;
    if (!g_need[i]) return;        // only S1 destinations are consumed downstream
    const int w = threadIdx.x >> 5;
    const int lane = threadIdx.x & 31;
    const int f = w * HID + lane * 2;
    const int s0 = g_off[i], s1 = g_off[i + 1];   // s1 > s0 (self loop)

    const float2 xrv = *(const float2*)(xlr + (size_t)i * 512 + 256 + f);
    const float2 atv = *(const float2*)(att + f);

    float acc0 = 0.f, acc1 = 0.f, den = 0.f;
    int p = s0;
    for (; p + 4 <= s1; p += 4) {
        int sA = __ldg(&g_src[p]);
        int sB = __ldg(&g_src[p + 1]);
        int sC = __ldg(&g_src[p + 2]);
        int sD = __ldg(&g_src[p + 3]);
        float2 xvA = *(const float2*)(xlr + (size_t)sA * 512 + f);
        float2 xvB = *(const float2*)(xlr + (size_t)sB * 512 + f);
        float2 xvC = *(const float2*)(xlr + (size_t)sC * 512 + f);
        float2 xvD = *(const float2*)(xlr + (size_t)sD * 512 + f);
        float sa = LEAKY(xvA.x + xrv.x) * atv.x + LEAKY(xvA.y + xrv.y) * atv.y;
        float sb = LEAKY(xvB.x + xrv.x) * atv.x + LEAKY(xvB.y + xrv.y) * atv.y;
        float sc = LEAKY(xvC.x + xrv.x) * atv.x + LEAKY(xvC.y + xrv.y) * atv.y;
        float sd = LEAKY(xvD.x + xrv.x) * atv.x + LEAKY(xvD.y + xrv.y) * atv.y;
#pragma unroll
        for (int o = 16; o; o >>= 1) {
            sa += __shfl_xor_sync(0xffffffffu, sa, o);
            sb += __shfl_xor_sync(0xffffffffu, sb, o);
            sc += __shfl_xor_sync(0xffffffffu, sc, o);
            sd += __shfl_xor_sync(0xffffffffu, sd, o);
        }
        float exa = __expf(sa), exb = __expf(sb);
        float exc = __expf(sc), exd = __expf(sd);
        acc0 += exa * xvA.x + exb * xvB.x + exc * xvC.x + exd * xvD.x;
        acc1 += exa * xvA.y + exb * xvB.y + exc * xvC.y + exd * xvD.y;
        den  += exa + exb + exc + exd;
    }
    for (; p < s1; p++) {
        int sA = __ldg(&g_src[p]);
        float2 xvA = *(const float2*)(xlr + (size_t)sA * 512 + f);
        float sa = LEAKY(xvA.x + xrv.x) * atv.x + LEAKY(xvA.y + xrv.y) * atv.y;
#pragma unroll
        for (int o = 16; o; o >>= 1) sa += __shfl_xor_sync(0xffffffffu, sa, o);
        float exa = __expf(sa);
        acc0 += exa * xvA.x; acc1 += exa * xvA.y; den += exa;
    }
    float rr = 1.f / (den + 1e-16f);
    float o0 = fmaxf(acc0 * rr + bias[f], 0.f);
    float o1 = fmaxf(acc1 * rr + bias[f + 1], 0.f);
    size_t oi = (size_t)i * DD + f;
    __nv_bfloat162 h, l;
    split_bf16(o0, h.x, l.x); split_bf16(o1, h.y, l.y);
    *(__nv_bfloat162*)&outH[oi] = h;
    *(__nv_bfloat162*)&outL[oi] = l;
}

// ================= GATv2 layer 2: only the BB indexed nodes ==================
// xl2: compact [cnt][256] via g_slot; xr2, out: compact [BB][256]
__global__ __launch_bounds__(128, 8)
void k_gat2(const int* __restrict__ idx,
            const float* __restrict__ xl2, const float* __restrict__ xr2,
            const float* __restrict__ att, const float* __restrict__ bias,
            float* __restrict__ outc) {
    const int b = blockIdx.x;
    const int node = idx[b];
    const int w = threadIdx.x >> 5;
    const int lane = threadIdx.x & 31;
    const int f = w * HID + lane * 2;
    const int s0 = g_off[node], s1 = g_off[node + 1];

    const float2 xrv = *(const float2*)(xr2 + (size_t)b * DD + f);
    const float2 atv = *(const float2*)(att + f);

    float acc0 = 0.f, acc1 = 0.f, den = 0.f;
    for (int p = s0; p < s1; p++) {
        int slot = g_slot[__ldg(&g_src[p])];
        float2 xv = *(const float2*)(xl2 + (size_t)slot * DD + f);
        float s = LEAKY(xv.x + xrv.x) * atv.x + LEAKY(xv.y + xrv.y) * atv.y;
#pragma unroll
        for (int o = 16; o; o >>= 1) s += __shfl_xor_sync(0xffffffffu, s, o);
        float ex = __expf(s);
        acc0 += ex * xv.x; acc1 += ex * xv.y; den += ex;
    }
    float rr = 1.f / (den + 1e-16f);
    size_t oi = (size_t)b * DD + f;
    outc[oi]     = fmaxf(acc0 * rr + bias[f], 0.f);
    outc[oi + 1] = fmaxf(acc1 * rr + bias[f + 1], 0.f);
}

// ================= dueling head (compact h3 by batch slot) ===================
__global__ void k_head(const int* __restrict__ idx,
                       const float* __restrict__ h3c,
                       const float* __restrict__ qw1, const float* __restrict__ qb1,
                       const float* __restrict__ qw2, const float* __restrict__ qb2,
                       const float* __restrict__ vw1, const float* __restrict__ vb1,
                       const float* __restrict__ vw2, const float* __restrict__ vb2,
                       float* __restrict__ out) {
    __shared__ float f[CAT];
    __shared__ float r0[DUEL_H], r1[DUEL_H], r2[DUEL_H];
    int b = blockIdx.x, t = threadIdx.x;
    int n = idx[b];
    for (int i = t; i < CAT; i += DUEL_H) {
        float v;
        if (i < HID)
            v = __bfloat162float(g_hh[(size_t)n * HID + i]) +
                __bfloat162float(g_hl[(size_t)n * HID + i]);
        else if (i < HID + DD)
            v = __bfloat162float(g_h2h[(size_t)n * DD + (i - HID)]) +
                __bfloat162float(g_h2l[(size_t)n * DD + (i - HID)]);
        else
            v = h3c[(size_t)b * DD + (i - HID - DD)];
        f[i] = v;
    }
    __syncthreads();
    float q = 0.f, v = 0.f;
#pragma unroll 4
    for (int k = 0; k < CAT; k++) {
        float fv = f[k];
        q += fv * qw1[(size_t)k * DUEL_H + t];
        v += fv * vw1[(size_t)k * DUEL_H + t];
    }
    q = fmaxf(q + qb1[t], 0.f);
    v = fmaxf(v + vb1[t], 0.f);
    r0[t] = q * qw2[t * 2 + 0];
    r1[t] = q * qw2[t * 2 + 1];
    r2[t] = v * vw2[t];
    __syncthreads();
    for (int o = 64; o; o >>= 1) {
        if (t < o) { r0[t] += r0[t + o]; r1[t] += r1[t + o]; r2[t] += r2[t + o]; }
        __syncthreads();
    }
    if (t == 0) {
        float q0 = r0[0] + qb2[0], q1 = r1[0] + qb2[1], vv = r2[0] + vb2[0];
        float m = 0.5f * (q0 + q1);
        out[b * 2 + 0] = q0 - m + vv;
        out[b * 2 + 1] = q1 - m + vv;
    }
}

// ================= launch ====================================================
extern "C" void kernel_launch(void* const* d_in, const int* in_sizes, int n_in,
                              void* d_out, int out_size) {
    const float* x      = (const float*)d_in[0];
    const int*   EI     = (const int*)  d_in[1];
    const int*   idx    = (const int*)  d_in[2];
    const float* enc_w1 = (const float*)d_in[3];
    const float* enc_b1 = (const float*)d_in[4];
    const float* enc_w2 = (const float*)d_in[5];
    const float* enc_b2 = (const float*)d_in[6];
    const float* wl1    = (const float*)d_in[7];
    const float* bl1    = (const float*)d_in[8];
    const float* wr1    = (const float*)d_in[9];
    const float* br1    = (const float*)d_in[10];
    const float* att1   = (const float*)d_in[11];
    const float* bias1  = (const float*)d_in[12];
    const float* wl2    = (const float*)d_in[13];
    const float* bl2    = (const float*)d_in[14];
    const float* wr2    = (const float*)d_in[15];
    const float* br2    = (const float*)d_in[16];
    const float* att2   = (const float*)d_in[17];
    const float* bias2  = (const float*)d_in[18];
    const float* q_w1   = (const float*)d_in[19];
    const float* q_b1   = (const float*)d_in[20];
    const float* q_w2   = (const float*)d_in[21];
    const float* q_b2   = (const float*)d_in[22];
    const float* v_w1   = (const float*)d_in[23];
    const float* v_b1   = (const float*)d_in[24];
    const float* v_w2   = (const float*)d_in[25];
    const float* v_b2   = (const float*)d_in[26];
    float* out = (float*)d_out;

    float *xlr, *xl2, *xr2, *h3, *b1, *b2;
    int* dcnt;
    __nv_bfloat16 *xh, *xlo, *h512h, *h512l, *hh, *hl, *h2h, *h2l;
    __nv_bfloat16 *ch2h, *ch2l, *gh2, *gl2, *wth, *wtl;
    cudaGetSymbolAddress((void**)&xlr,  g_xlr);
    cudaGetSymbolAddress((void**)&xl2,  g_xl2);
    cudaGetSymbolAddress((void**)&xr2,  g_xr2);
    cudaGetSymbolAddress((void**)&h3,   g_h3);
    cudaGetSymbolAddress((void**)&b1,   g_b1);
    cudaGetSymbolAddress((void**)&b2,   g_b2);
    cudaGetSymbolAddress((void**)&dcnt, g_cnt);
    cudaGetSymbolAddress((void**)&xh,   g_xh);
    cudaGetSymbolAddress((void**)&xlo,  g_xlo);
    cudaGetSymbolAddress((void**)&h512h, g_h512h);
    cudaGetSymbolAddress((void**)&h512l, g_h512l);
    cudaGetSymbolAddress((void**)&hh,   g_hh);
    cudaGetSymbolAddress((void**)&hl,   g_hl);
    cudaGetSymbolAddress((void**)&h2h,  g_h2h);
    cudaGetSymbolAddress((void**)&h2l,  g_h2l);
    cudaGetSymbolAddress((void**)&ch2h, g_ch2h);
    cudaGetSymbolAddress((void**)&ch2l, g_ch2l);
    cudaGetSymbolAddress((void**)&gh2,  g_gh2);
    cudaGetSymbolAddress((void**)&gl2,  g_gl2);
    cudaGetSymbolAddress((void**)&wth,  g_wth);
    cudaGetSymbolAddress((void**)&wtl,  g_wtl);

    // Lazy one-time host resources for fork/join (graph-capture legal)
    static cudaStream_t s2 = nullptr, s3 = nullptr;
    static cudaEvent_t evFork = nullptr, evJoin = nullptr, evPrep = nullptr;
    static cudaEvent_t evG = nullptr, evXr = nullptr;
    if (!s2) {
        cudaStreamCreateWithFlags(&s2, cudaStreamNonBlocking);
        cudaStreamCreateWithFlags(&s3, cudaStreamNonBlocking);
        cudaEventCreateWithFlags(&evFork, cudaEventDisableTiming);
        cudaEventCreateWithFlags(&evJoin, cudaEventDisableTiming);
        cudaEventCreateWithFlags(&evPrep, cudaEventDisableTiming);
        cudaEventCreateWithFlags(&evG, cudaEventDisableTiming);
        cudaEventCreateWithFlags(&evXr, cudaEventDisableTiming);
    }

    const int SM_64_64 = 2 * (2 * 64 + 2 * 64) * STR * 2;     // 40,960 B
    cudaFuncSetAttribute((const void*)k_mma<64, 64, 3, 1, 0, 1>, cudaFuncAttributeMaxDynamicSharedMemorySize, SM_64_64);
    cudaFuncSetAttribute((const void*)k_mma<64, 64, 3, 0, 1, 0>, cudaFuncAttributeMaxDynamicSharedMemorySize, SM_64_64);

    const int MT64 = (NN + 63) / 64;     // 313

    // ---- fork: CSR build + S1 slice on s2; weight prep on s3 ----
    cudaEventRecord(evFork, 0);
    cudaStreamWaitEvent(s2, evFork, 0);
    cudaStreamWaitEvent(s3, evFork, 0);
    k_zero_deg<<<(NN + 255) / 256, 256, 0, s2>>>();
    k_count<<<(EP + 255) / 256, 256, 0, s2>>>(EI);
    k_scan<<<1, 1024, 0, s2>>>();
    k_fill<<<(EP + 255) / 256, 256, 0, s2>>>(EI);
    k_mark<<<BB, 128, 0, s2>>>(idx);
    k_compact<<<1, 1024, 0, s2>>>();
    cudaEventRecord(evJoin, s2);

    k_wprep<<<896, 256, 0, s3>>>(enc_w1, enc_w2, wl1, wr1, wl2, wr2);
    k_bprep<<<4, 256, 0, s3>>>(bl1, br1, bl2, br2);
    cudaEventRecord(evPrep, s3);

    // ---- main stream: activation split, then GEMM chain ----
    k_split_x<<<(NN * HID / 4 + 255) / 256, 256>>>(x);
    cudaStreamWaitEvent(0, evPrep, 0);

    // enc1: [NN,64] @ [64,512] -> h512 (bf16 hi/lo), relu
    k_mma<64, 64, 3, 1, 0, 1><<<dim3(ENC_H / 64, MT64), 256, SM_64_64>>>(
        xh, xlo, wth + WOFF_ENC1, wtl + WOFF_ENC1, enc_b1, nullptr, h512h, h512l, NN, 64, ENC_H, nullptr);
    // enc2: [NN,512] @ [512,64] -> h (bf16 hi/lo only), relu
    k_mma<64, 64, 3, 1, 0, 1><<<dim3(1, MT64), 256, SM_64_64>>>(
        h512h, h512l, wth + WOFF_ENC2, wtl + WOFF_ENC2, enc_b2, nullptr, hh, hl, NN, ENC_H, HID, nullptr);

    // conv1: combined [xl|xr] transform, N=512, K=64
    k_mma<64, 64, 3, 0, 1, 0><<<dim3(8, MT64), 256, SM_64_64>>>(
        hh, hl, wth + WOFF_W1, wtl + WOFF_W1, b1, xlr, nullptr, nullptr, NN, HID, 512, nullptr);

    // ---- join: CSR + S1 must be ready before gat1 ----
    cudaStreamWaitEvent(0, evJoin, 0);
    k_gat<<<NN, 128>>>(xlr, att1, bias1, h2h, h2l);
    cudaEventRecord(evG, 0);

    // side stream: gather indexed h2 rows, small xr2 GEMM (M=128, K=256, N=256)
    cudaStreamWaitEvent(s2, evG, 0);
    k_gidx<<<BB, 128, 0, s2>>>(idx);
    k_mma<64, 64, 3, 0, 1, 0><<<dim3(4, 2), 256, SM_64_64, s2>>>(
        gh2, gl2, wth + WOFF_W2 + 65536, wtl + WOFF_W2 + 65536, b2 + 256,
        xr2, nullptr, nullptr, BB, DD, DD, nullptr);
    cudaEventRecord(evXr, s2);

    // main: compact S1 h2 rows, conv2 xl-only over S1 (dynamic M)
    k_gath2<<<NN, 128>>>();
    k_mma<64, 64, 3, 0, 1, 0><<<dim3(4, MT64), 256, SM_64_64>>>(
        ch2h, ch2l, wth + WOFF_W2, wtl + WOFF_W2, b2, xl2, nullptr, nullptr, NN, DD, DD, dcnt);

    // gat2 over the 128 indexed nodes only (xl2 via slot indirection)
    cudaStreamWaitEvent(0, evXr, 0);
    k_gat2<<<BB, 128>>>(idx, xl2, xr2, att2, bias2, h3);

    // heads
    k_head<<<BB, DUEL_H>>>(idx, h3,
                           q_w1, q_b1, q_w2, q_b2, v_w1, v_b1, v_w2, v_b2, out);
}